// round 3
// baseline (speedup 1.0000x reference)
#include <cuda_runtime.h>

#define BATCH 2
#define NPTS  16384
#define NKP   4096
#define TOTKP (BATCH*NKP)
#define CCAP  384
#define R2A_CONST ((float)(0.8*0.8))
#define R2B_CONST ((float)(1.6*1.6))

__device__ int   g_kp_idx[TOTKP];
__device__ float g_kp_xyz[TOTKP*3];
__device__ float g_cand_d[TOTKP*CCAP];
__device__ int   g_cand_i[TOTKP*CCAP];
__device__ int   g_cand_cnt[TOTKP];
__device__ int   g_nbr[TOTKP*32];
__device__ int   g_cnt_a[TOTKP];
__device__ int   g_cnt_b[TOTKP];
__device__ float g_pooled[TOTKP*512];

__device__ __forceinline__ float dist2_ref(float dx, float dy, float dz) {
    return __fadd_rn(__fadd_rn(__fmul_rn(dx,dx), __fmul_rn(dy,dy)), __fmul_rn(dz,dz));
}

// ============ K1: FPS, one block per batch ============
extern __shared__ float smem_fps[];
__global__ __launch_bounds__(1024,1) void fps_kernel(const float* __restrict__ clouds) {
    int b = blockIdx.x;
    float* sx = smem_fps; float* sy = smem_fps + NPTS; float* sz = smem_fps + 2*NPTS;
    __shared__ float rv[32];
    __shared__ int   ri[32];
    __shared__ int   s_last;
    const float* cb = clouds + (size_t)b*4*NPTS;
    int t = threadIdx.x;
    for (int i = t; i < NPTS; i += 1024) {
        sx[i] = cb[i]; sy[i] = cb[NPTS+i]; sz[i] = cb[2*NPTS+i];
    }
    float dmin[16];
    #pragma unroll
    for (int j = 0; j < 16; j++) dmin[j] = 1e10f;
    if (t == 0) s_last = 0;
    __syncthreads();

    for (int it = 0; it < NKP; ++it) {
        int last = s_last;
        if (t == 0) g_kp_idx[b*NKP + it] = last;  // scan emits carry before update
        if (it == NKP-1) break;
        float lx = sx[last], ly = sy[last], lz = sz[last];
        float bestv = -1.0f; int besti = 0;
        #pragma unroll
        for (int j = 0; j < 16; j++) {
            int i = t + j*1024;
            float d  = dist2_ref(sx[i]-lx, sy[i]-ly, sz[i]-lz);
            float nd = fminf(dmin[j], d);
            dmin[j] = nd;
            if (nd > bestv) { bestv = nd; besti = i; }  // strict > keeps lowest idx
        }
        #pragma unroll
        for (int off = 16; off > 0; off >>= 1) {
            float ov = __shfl_down_sync(0xffffffffu, bestv, off);
            int   oi = __shfl_down_sync(0xffffffffu, besti, off);
            if (ov > bestv || (ov == bestv && oi < besti)) { bestv = ov; besti = oi; }
        }
        if ((t & 31) == 0) { rv[t>>5] = bestv; ri[t>>5] = besti; }
        __syncthreads();
        if (t < 32) {
            bestv = rv[t]; besti = ri[t];
            #pragma unroll
            for (int off = 16; off > 0; off >>= 1) {
                float ov = __shfl_down_sync(0xffffffffu, bestv, off);
                int   oi = __shfl_down_sync(0xffffffffu, besti, off);
                if (ov > bestv || (ov == bestv && oi < besti)) { bestv = ov; besti = oi; }
            }
            if (t == 0) s_last = besti;
        }
        __syncthreads();
    }
    __syncthreads();
    for (int k = t; k < NKP; k += 1024) {
        int idx = g_kp_idx[b*NKP + k];
        g_kp_xyz[(b*NKP+k)*3+0] = sx[idx];
        g_kp_xyz[(b*NKP+k)*3+1] = sy[idx];
        g_kp_xyz[(b*NKP+k)*3+2] = sz[idx];
    }
}

// ============ K2: ball-query candidates (16 kp / block, 4 per warp) ============
__global__ __launch_bounds__(128) void ballq_kernel(const float* __restrict__ clouds) {
    int b = blockIdx.y, kp0 = blockIdx.x * 16;
    __shared__ float4 spt[2048];
    __shared__ int    scnt[16];
    int t = threadIdx.x, lane = t & 31, w = t >> 5;
    float kx[4], ky[4], kz[4];
    #pragma unroll
    for (int q = 0; q < 4; q++) {
        int kk = b*NKP + kp0 + w*4 + q;
        kx[q] = g_kp_xyz[kk*3+0]; ky[q] = g_kp_xyz[kk*3+1]; kz[q] = g_kp_xyz[kk*3+2];
    }
    if (t < 16) scnt[t] = 0;
    const float* cb = clouds + (size_t)b*4*NPTS;
    for (int tile = 0; tile < NPTS; tile += 2048) {
        __syncthreads();
        for (int i = t; i < 2048; i += 128) {
            int gi = tile + i;
            spt[i] = make_float4(cb[gi], cb[NPTS+gi], cb[2*NPTS+gi], 0.f);
        }
        __syncthreads();
        for (int p = lane; p < 2048; p += 32) {
            float4 P = spt[p];
            int gi = tile + p;
            #pragma unroll
            for (int q = 0; q < 4; q++) {
                float d2 = dist2_ref(kx[q]-P.x, ky[q]-P.y, kz[q]-P.z);
                bool hit = d2 < R2B_CONST;
                unsigned m = __ballot_sync(0xffffffffu, hit);
                if (m) {
                    int kloc = w*4 + q;
                    int leader = __ffs(m) - 1;
                    int base = 0;
                    if (lane == leader) { base = scnt[kloc]; scnt[kloc] = base + __popc(m); }
                    base = __shfl_sync(0xffffffffu, base, leader);
                    if (hit) {
                        int pos = base + __popc(m & ((1u<<lane) - 1u));
                        if (pos < CCAP) {
                            int kk = b*NKP + kp0 + kloc;
                            g_cand_d[kk*CCAP + pos] = d2;
                            g_cand_i[kk*CCAP + pos] = gi;
                        }
                    }
                }
            }
        }
    }
    __syncthreads();
    if (t < 16) g_cand_cnt[b*NKP + kp0 + t] = scnt[t];
}

// ============ K3: rank candidates (one warp per keypoint) ============
__global__ __launch_bounds__(256) void select_kernel() {
    __shared__ float sd[8*CCAP];
    __shared__ int   si[8*CCAP];
    int w = threadIdx.x >> 5, lane = threadIdx.x & 31;
    int kp = blockIdx.x * 8 + w;
    float* swd = sd + w*CCAP; int* swi = si + w*CCAP;
    int n = g_cand_cnt[kp]; if (n > CCAP) n = CCAP;
    for (int c = lane; c < n; c += 32) {
        swd[c] = g_cand_d[kp*CCAP + c];
        swi[c] = g_cand_i[kp*CCAP + c];
    }
    __syncwarp();
    int na = 0;
    for (int c = lane; c < n; c += 32) {
        float dc = swd[c];
        int rank = 0;
        for (int c2 = 0; c2 < n; c2++) {
            float dv = swd[c2];
            rank += (dv < dc) || (dv == dc && c2 < c);  // insertion order == idx order
        }
        if (rank < 32) g_nbr[kp*32 + rank] = swi[c];
        if (rank < 16 && dc < R2A_CONST) na++;  // within-r_a prefix of ranked list
    }
    #pragma unroll
    for (int off = 16; off > 0; off >>= 1) na += __shfl_down_sync(0xffffffffu, na, off);
    if (lane == 0) {
        g_cnt_a[kp] = na;
        g_cnt_b[kp] = (n < 32) ? n : 32;
    }
}

// ============ K4: PointNet MLP + max pool (one block per keypoint) ============
__global__ __launch_bounds__(256) void mlp_kernel(const float* __restrict__ clouds,
                                                  const float* __restrict__ w1a,
                                                  const float* __restrict__ w2a,
                                                  const float* __restrict__ w1b,
                                                  const float* __restrict__ w2b) {
    int kp = blockIdx.x;
    int b  = kp >> 12;
    __shared__ float sg[32][5];
    __shared__ float h1bt[128*32];
    __shared__ float h1at[128*16];
    __shared__ int   s_ca, s_cb;
    int t = threadIdx.x;
    if (t == 0) { s_ca = g_cnt_a[kp]; s_cb = g_cnt_b[kp]; }
    __syncthreads();
    int ca = s_ca, cb2 = s_cb;

    if (t < 32 && t < cb2) {
        int pi = g_nbr[kp*32 + t];
        const float* cbase = clouds + (size_t)b*4*NPTS;
        sg[t][0] = cbase[pi]        - g_kp_xyz[kp*3+0];
        sg[t][1] = cbase[NPTS+pi]   - g_kp_xyz[kp*3+1];
        sg[t][2] = cbase[2*NPTS+pi] - g_kp_xyz[kp*3+2];
        sg[t][3] = cbase[3*NPTS+pi];
    }
    __syncthreads();

    for (int e = t; e < 128*32; e += 256) {
        int j = e & 31, i = e >> 5;
        float v = 0.f;
        if (j < cb2) {
            float a = __fmul_rn(sg[j][0], w1b[i]);
            a = fmaf(sg[j][1], w1b[128+i], a);
            a = fmaf(sg[j][2], w1b[256+i], a);
            a = fmaf(sg[j][3], w1b[384+i], a);
            v = fmaxf(a, 0.f);
        }
        h1bt[i*32 + j] = v;
    }
    for (int e = t; e < 128*16; e += 256) {
        int j = e & 15, i = e >> 4;
        float v = 0.f;
        if (j < ca) {
            float a = __fmul_rn(sg[j][0], w1a[i]);
            a = fmaf(sg[j][1], w1a[128+i], a);
            a = fmaf(sg[j][2], w1a[256+i], a);
            a = fmaf(sg[j][3], w1a[384+i], a);
            v = fmaxf(a, 0.f);
        }
        h1at[i*16 + j] = v;
    }
    __syncthreads();

    float accb[32];
    #pragma unroll
    for (int j = 0; j < 32; j++) accb[j] = 0.f;
    for (int i = 0; i < 128; i++) {
        float wv = __ldg(&w2b[i*256 + t]);
        const float4* hr = reinterpret_cast<const float4*>(h1bt + i*32);
        #pragma unroll
        for (int j4 = 0; j4 < 8; j4++) {
            float4 h = hr[j4];
            accb[j4*4+0] = fmaf(h.x, wv, accb[j4*4+0]);
            accb[j4*4+1] = fmaf(h.y, wv, accb[j4*4+1]);
            accb[j4*4+2] = fmaf(h.z, wv, accb[j4*4+2]);
            accb[j4*4+3] = fmaf(h.w, wv, accb[j4*4+3]);
        }
    }
    float bestb = 0.f;
    #pragma unroll
    for (int j = 0; j < 32; j++) bestb = fmaxf(bestb, accb[j]);

    float acca[16];
    #pragma unroll
    for (int j = 0; j < 16; j++) acca[j] = 0.f;
    for (int i = 0; i < 128; i++) {
        float wv = __ldg(&w2a[i*256 + t]);
        const float4* hr = reinterpret_cast<const float4*>(h1at + i*16);
        #pragma unroll
        for (int j4 = 0; j4 < 4; j4++) {
            float4 h = hr[j4];
            acca[j4*4+0] = fmaf(h.x, wv, acca[j4*4+0]);
            acca[j4*4+1] = fmaf(h.y, wv, acca[j4*4+1]);
            acca[j4*4+2] = fmaf(h.z, wv, acca[j4*4+2]);
            acca[j4*4+3] = fmaf(h.w, wv, acca[j4*4+3]);
        }
    }
    float besta = 0.f;
    #pragma unroll
    for (int j = 0; j < 16; j++) besta = fmaxf(besta, acca[j]);

    g_pooled[kp*512 + t]       = besta;
    g_pooled[kp*512 + 256 + t] = bestb;
}

// ============ K5: fusion + output (16 kp per block) ============
__global__ __launch_bounds__(128) void fuse_kernel(const float* __restrict__ wf,
                                                   float* __restrict__ out) {
    int kp0 = blockIdx.x * 16;
    __shared__ float sp[512*16];
    int t = threadIdx.x;
    for (int e = t; e < 512*16; e += 128) {
        int c = e & 511, q = e >> 9;
        sp[c*16 + q] = g_pooled[(size_t)(kp0 + q)*512 + c];
    }
    __syncthreads();
    float acc[16];
    #pragma unroll
    for (int q = 0; q < 16; q++) acc[q] = 0.f;
    for (int c = 0; c < 512; c++) {
        float wv = __ldg(&wf[c*128 + t]);
        const float4* pr = reinterpret_cast<const float4*>(sp + c*16);
        #pragma unroll
        for (int q4 = 0; q4 < 4; q4++) {
            float4 p = pr[q4];
            acc[q4*4+0] = fmaf(p.x, wv, acc[q4*4+0]);
            acc[q4*4+1] = fmaf(p.y, wv, acc[q4*4+1]);
            acc[q4*4+2] = fmaf(p.z, wv, acc[q4*4+2]);
            acc[q4*4+3] = fmaf(p.w, wv, acc[q4*4+3]);
        }
    }
    #pragma unroll
    for (int q = 0; q < 16; q++)
        out[(size_t)(kp0+q)*131 + 3 + t] = fmaxf(acc[q], 0.f);
    if (t < 48) {
        int q = t / 3, comp = t % 3;
        out[(size_t)(kp0+q)*131 + comp] = g_kp_xyz[(kp0+q)*3 + comp];
    }
}

extern "C" void kernel_launch(void* const* d_in, const int* in_sizes, int n_in,
                              void* d_out, int out_size) {
    const float* clouds = (const float*)d_in[0];
    const float* w1a    = (const float*)d_in[1];
    const float* w2a    = (const float*)d_in[2];
    const float* w1b    = (const float*)d_in[3];
    const float* w2b    = (const float*)d_in[4];
    const float* wf     = (const float*)d_in[5];
    float* out = (float*)d_out;

    cudaFuncSetAttribute(fps_kernel, cudaFuncAttributeMaxDynamicSharedMemorySize, 3*NPTS*4);
    fps_kernel<<<BATCH, 1024, 3*NPTS*4>>>(clouds);

    dim3 g2(NKP/16, BATCH);
    ballq_kernel<<<g2, 128>>>(clouds);
    select_kernel<<<TOTKP/8, 256>>>();
    mlp_kernel<<<TOTKP, 256>>>(clouds, w1a, w2a, w1b, w2b);
    fuse_kernel<<<TOTKP/16, 128>>>(wf, out);
}

// round 4
// speedup vs baseline: 1.7459x; 1.7459x over previous
#include <cuda_runtime.h>

#define BATCH 2
#define NPTS  16384
#define NKP   4096
#define TOTKP (BATCH*NKP)
#define CCAP  384
#define R2A_CONST ((float)(0.8*0.8))
#define R2B_CONST ((float)(1.6*1.6))
#define NTHR  1024
#define PPT   16
#define NCELLS 512

__device__ float g_kp_xyz[TOTKP*3];
__device__ int   g_kp_sorted[TOTKP];
__device__ float g_cand_d[TOTKP*CCAP];
__device__ int   g_cand_i[TOTKP*CCAP];
__device__ int   g_cand_cnt[TOTKP];
__device__ int   g_nbr[TOTKP*32];
__device__ int   g_cnt_a[TOTKP];
__device__ int   g_cnt_b[TOTKP];
__device__ float g_pooled[TOTKP*512];

__device__ __forceinline__ float dist2_ref(float dx, float dy, float dz) {
    return __fadd_rn(__fadd_rn(__fmul_rn(dx,dx), __fmul_rn(dy,dy)), __fmul_rn(dz,dz));
}
// monotone float<->uint encode for atomic min/max
__device__ __forceinline__ unsigned fenc(float f) {
    unsigned u = __float_as_uint(f);
    return (u & 0x80000000u) ? ~u : (u | 0x80000000u);
}
__device__ __forceinline__ float fdec(unsigned u) {
    return __uint_as_float((u & 0x80000000u) ? (u & 0x7fffffffu) : ~u);
}
__device__ __forceinline__ int mort4(int v) {  // spread 4 bits -> 8
    v = (v | (v << 2)) & 0x33;
    v = (v | (v << 1)) & 0x55;
    return v;
}

// ============ K1: FPS with spatial-bucket skipping (one block per batch) ============
// dynamic smem: sxT|syT|szT (transposed sorted coords), spermT (u16 orig idx),
// hist (512), warp caches, misc scalars.
extern __shared__ unsigned char dsm[];

__global__ __launch_bounds__(NTHR,1) void fps_kernel(const float* __restrict__ clouds) {
    int b = blockIdx.x;
    float* sxT = (float*)dsm;
    float* syT = sxT + NPTS;
    float* szT = syT + NPTS;
    unsigned short* spermT = (unsigned short*)(szT + NPTS);
    unsigned int*   hist   = (unsigned int*)(spermT + NPTS);
    float* wv = (float*)(hist + NCELLS);
    int*   wo = (int*)(wv + 32);
    int*   ws = (int*)(wo + 32);
    int*   s_misc = ws + 32;           // [0]=s_last, [1..6]=bbox enc

    const float* cb = clouds + (size_t)b*4*NPTS;
    int t = threadIdx.x, lane = t & 31, w = t >> 5;

    // --- setup phase A: global bbox + zero hist ---
    if (t < 3)      s_misc[1+t] = (int)0xFFFFFFFFu;   // mins (encoded)
    else if (t < 6) s_misc[1+t-3+3] = 0;              // placeholder (fixed below)
    if (t >= 3 && t < 6) s_misc[1+t] = 0;             // maxs (encoded)
    for (int c = t; c < NCELLS; c += NTHR) hist[c] = 0;
    __syncthreads();
    {
        float mnx=1e30f,mny=1e30f,mnz=1e30f,mxx=-1e30f,mxy=-1e30f,mxz=-1e30f;
        for (int j = 0; j < PPT; j++) {
            int i = t + j*NTHR;
            float x = cb[i], y = cb[NPTS+i], z = cb[2*NPTS+i];
            mnx = fminf(mnx,x); mny = fminf(mny,y); mnz = fminf(mnz,z);
            mxx = fmaxf(mxx,x); mxy = fmaxf(mxy,y); mxz = fmaxf(mxz,z);
        }
        #pragma unroll
        for (int off = 16; off > 0; off >>= 1) {
            mnx = fminf(mnx, __shfl_down_sync(0xffffffffu, mnx, off));
            mny = fminf(mny, __shfl_down_sync(0xffffffffu, mny, off));
            mnz = fminf(mnz, __shfl_down_sync(0xffffffffu, mnz, off));
            mxx = fmaxf(mxx, __shfl_down_sync(0xffffffffu, mxx, off));
            mxy = fmaxf(mxy, __shfl_down_sync(0xffffffffu, mxy, off));
            mxz = fmaxf(mxz, __shfl_down_sync(0xffffffffu, mxz, off));
        }
        if (lane == 0) {
            atomicMin((unsigned*)&s_misc[1], fenc(mnx));
            atomicMin((unsigned*)&s_misc[2], fenc(mny));
            atomicMin((unsigned*)&s_misc[3], fenc(mnz));
            atomicMax((unsigned*)&s_misc[4], fenc(mxx));
            atomicMax((unsigned*)&s_misc[5], fenc(mxy));
            atomicMax((unsigned*)&s_misc[6], fenc(mxz));
        }
    }
    __syncthreads();
    float gminx = fdec((unsigned)s_misc[1]), gminy = fdec((unsigned)s_misc[2]), gminz = fdec((unsigned)s_misc[3]);
    float grx = 16.0f / fmaxf(fdec((unsigned)s_misc[4]) - gminx, 1e-9f);
    float gry = 16.0f / fmaxf(fdec((unsigned)s_misc[5]) - gminy, 1e-9f);
    float grz = 2.0f  / fmaxf(fdec((unsigned)s_misc[6]) - gminz, 1e-9f);

    // --- phase B: histogram ---
    for (int j = 0; j < PPT; j++) {
        int i = t + j*NTHR;
        int cx = min(15, (int)((cb[i]        - gminx) * grx));
        int cy = min(15, (int)((cb[NPTS+i]   - gminy) * gry));
        int cz = min(1,  (int)((cb[2*NPTS+i] - gminz) * grz));
        int cell = (((mort4(cy) << 1) | mort4(cx)) << 1) | cz;
        atomicAdd(&hist[cell], 1u);
    }
    __syncthreads();
    // --- exclusive prefix sum over 512 cells (Hillis-Steele) ---
    for (int off = 1; off < NCELLS; off <<= 1) {
        unsigned v = 0;
        if (t < NCELLS && t >= off) v = hist[t-off];
        __syncthreads();
        if (t < NCELLS) hist[t] += v;
        __syncthreads();
    }
    {
        unsigned v = (t == 0) ? 0u : ((t < NCELLS) ? hist[t-1] : 0u);
        __syncthreads();
        if (t < NCELLS) hist[t] = v;
        __syncthreads();
    }
    // --- scatter (transposed layout: sorted pos p -> phys (p&15)*1024 + (p>>4)) ---
    for (int j = 0; j < PPT; j++) {
        int i = t + j*NTHR;
        float x = cb[i], y = cb[NPTS+i], z = cb[2*NPTS+i];
        int cx = min(15, (int)((x - gminx) * grx));
        int cy = min(15, (int)((y - gminy) * gry));
        int cz = min(1,  (int)((z - gminz) * grz));
        int cell = (((mort4(cy) << 1) | mort4(cx)) << 1) | cz;
        int p = (int)atomicAdd(&hist[cell], 1u);
        int phys = (p & 15)*NTHR + (p >> 4);
        sxT[phys] = x; syT[phys] = y; szT[phys] = z;
        spermT[phys] = (unsigned short)i;
        if (i == 0) s_misc[0] = p;   // sorted position of orig point 0
    }
    __syncthreads();

    // --- per-thread bucket state ---
    float dmin[PPT];
    float bxmin=1e30f, bymin=1e30f, bzmin=1e30f, bxmax=-1e30f, bymax=-1e30f, bzmax=-1e30f;
    #pragma unroll
    for (int j = 0; j < PPT; j++) {
        dmin[j] = 1e10f;
        float x = sxT[j*NTHR + t], y = syT[j*NTHR + t], z = szT[j*NTHR + t];
        bxmin = fminf(bxmin,x); bymin = fminf(bymin,y); bzmin = fminf(bzmin,z);
        bxmax = fmaxf(bxmax,x); bymax = fmaxf(bymax,y); bzmax = fmaxf(bzmax,z);
    }
    float bestv = 1e10f; int bestorig = 0x7fffffff; int bestsorted = t*PPT;
    bool wvalid = false;

    // --- main FPS loop ---
    for (int it = 0; it < NKP; ++it) {
        int last = s_misc[0];
        if (t == 0) g_kp_sorted[b*NKP + it] = last;
        if (it == NKP-1) break;

        int lphys = (last & 15)*NTHR + (last >> 4);
        float lx = sxT[lphys], ly = syT[lphys], lz = szT[lphys];

        // bbox min-distance^2 (conservative skip with margin)
        float dx = fmaxf(fmaxf(bxmin - lx, lx - bxmax), 0.f);
        float dy = fmaxf(fmaxf(bymin - ly, ly - bymax), 0.f);
        float dz = fmaxf(fmaxf(bzmin - lz, lz - bzmax), 0.f);
        float d2b = fmaf(dx, dx, fmaf(dy, dy, dz*dz));
        bool need = (d2b * 0.99999f) < bestv;

        if (need) {
            float bv = -1.f; int bo = 0x7fffffff, bs = t*PPT;
            #pragma unroll
            for (int j = 0; j < PPT; j++) {
                int phys = j*NTHR + t;
                float d  = dist2_ref(sxT[phys]-lx, syT[phys]-ly, szT[phys]-lz);
                float nd = fminf(dmin[j], d);
                dmin[j] = nd;
                int o = (int)spermT[phys];
                if (nd > bv || (nd == bv && o < bo)) { bv = nd; bo = o; bs = t*PPT + j; }
            }
            bestv = bv; bestorig = bo; bestsorted = bs;
        }
        unsigned m = __ballot_sync(0xffffffffu, need);
        if (m != 0u || !wvalid) {
            wvalid = true;
            float v = bestv; int o = bestorig, s = bestsorted;
            #pragma unroll
            for (int off = 16; off > 0; off >>= 1) {
                float v2 = __shfl_down_sync(0xffffffffu, v, off);
                int   o2 = __shfl_down_sync(0xffffffffu, o, off);
                int   s2 = __shfl_down_sync(0xffffffffu, s, off);
                if (v2 > v || (v2 == v && o2 < o)) { v = v2; o = o2; s = s2; }
            }
            if (lane == 0) { wv[w] = v; wo[w] = o; ws[w] = s; }
        }
        __syncthreads();
        if (t < 32) {
            float v = wv[t]; int o = wo[t], s = ws[t];
            #pragma unroll
            for (int off = 16; off > 0; off >>= 1) {
                float v2 = __shfl_down_sync(0xffffffffu, v, off);
                int   o2 = __shfl_down_sync(0xffffffffu, o, off);
                int   s2 = __shfl_down_sync(0xffffffffu, s, off);
                if (v2 > v || (v2 == v && o2 < o)) { v = v2; o = o2; s = s2; }
            }
            if (t == 0) s_misc[0] = s;
        }
        __syncthreads();
    }
    __syncthreads();
    // --- emit keypoint coords ---
    for (int k = t; k < NKP; k += NTHR) {
        int p = g_kp_sorted[b*NKP + k];
        int phys = (p & 15)*NTHR + (p >> 4);
        g_kp_xyz[(b*NKP+k)*3+0] = sxT[phys];
        g_kp_xyz[(b*NKP+k)*3+1] = syT[phys];
        g_kp_xyz[(b*NKP+k)*3+2] = szT[phys];
    }
}

// ============ K2: ball-query candidates (16 kp / block, 4 per warp) ============
__global__ __launch_bounds__(128) void ballq_kernel(const float* __restrict__ clouds) {
    int b = blockIdx.y, kp0 = blockIdx.x * 16;
    __shared__ float4 spt[2048];
    __shared__ int    scnt[16];
    int t = threadIdx.x, lane = t & 31, w = t >> 5;
    float kx[4], ky[4], kz[4];
    #pragma unroll
    for (int q = 0; q < 4; q++) {
        int kk = b*NKP + kp0 + w*4 + q;
        kx[q] = g_kp_xyz[kk*3+0]; ky[q] = g_kp_xyz[kk*3+1]; kz[q] = g_kp_xyz[kk*3+2];
    }
    if (t < 16) scnt[t] = 0;
    const float* cb = clouds + (size_t)b*4*NPTS;
    for (int tile = 0; tile < NPTS; tile += 2048) {
        __syncthreads();
        for (int i = t; i < 2048; i += 128) {
            int gi = tile + i;
            spt[i] = make_float4(cb[gi], cb[NPTS+gi], cb[2*NPTS+gi], 0.f);
        }
        __syncthreads();
        for (int p = lane; p < 2048; p += 32) {
            float4 P = spt[p];
            int gi = tile + p;
            #pragma unroll
            for (int q = 0; q < 4; q++) {
                float d2 = dist2_ref(kx[q]-P.x, ky[q]-P.y, kz[q]-P.z);
                bool hit = d2 < R2B_CONST;
                unsigned m = __ballot_sync(0xffffffffu, hit);
                if (m) {
                    int kloc = w*4 + q;
                    int leader = __ffs(m) - 1;
                    int base = 0;
                    if (lane == leader) { base = scnt[kloc]; scnt[kloc] = base + __popc(m); }
                    base = __shfl_sync(0xffffffffu, base, leader);
                    if (hit) {
                        int pos = base + __popc(m & ((1u<<lane) - 1u));
                        if (pos < CCAP) {
                            int kk = b*NKP + kp0 + kloc;
                            g_cand_d[kk*CCAP + pos] = d2;
                            g_cand_i[kk*CCAP + pos] = gi;
                        }
                    }
                }
            }
        }
    }
    __syncthreads();
    if (t < 16) g_cand_cnt[b*NKP + kp0 + t] = scnt[t];
}

// ============ K3: rank candidates (one warp per keypoint) ============
__global__ __launch_bounds__(256) void select_kernel() {
    __shared__ float sd[8*CCAP];
    __shared__ int   si[8*CCAP];
    int w = threadIdx.x >> 5, lane = threadIdx.x & 31;
    int kp = blockIdx.x * 8 + w;
    float* swd = sd + w*CCAP; int* swi = si + w*CCAP;
    int n = g_cand_cnt[kp]; if (n > CCAP) n = CCAP;
    for (int c = lane; c < n; c += 32) {
        swd[c] = g_cand_d[kp*CCAP + c];
        swi[c] = g_cand_i[kp*CCAP + c];
    }
    __syncwarp();
    int na = 0;
    for (int c = lane; c < n; c += 32) {
        float dc = swd[c];
        int rank = 0;
        for (int c2 = 0; c2 < n; c2++) {
            float dv = swd[c2];
            rank += (dv < dc) || (dv == dc && c2 < c);
        }
        if (rank < 32) g_nbr[kp*32 + rank] = swi[c];
        if (rank < 16 && dc < R2A_CONST) na++;
    }
    #pragma unroll
    for (int off = 16; off > 0; off >>= 1) na += __shfl_down_sync(0xffffffffu, na, off);
    if (lane == 0) {
        g_cnt_a[kp] = na;
        g_cnt_b[kp] = (n < 32) ? n : 32;
    }
}

// ============ K4: PointNet MLP + max pool (one block per keypoint) ============
__global__ __launch_bounds__(256) void mlp_kernel(const float* __restrict__ clouds,
                                                  const float* __restrict__ w1a,
                                                  const float* __restrict__ w2a,
                                                  const float* __restrict__ w1b,
                                                  const float* __restrict__ w2b) {
    int kp = blockIdx.x;
    int b  = kp >> 12;
    __shared__ float sg[32][5];
    __shared__ float h1bt[128*32];
    __shared__ float h1at[128*16];
    __shared__ int   s_ca, s_cb;
    int t = threadIdx.x;
    if (t == 0) { s_ca = g_cnt_a[kp]; s_cb = g_cnt_b[kp]; }
    __syncthreads();
    int ca = s_ca, cb2 = s_cb;

    if (t < 32 && t < cb2) {
        int pi = g_nbr[kp*32 + t];
        const float* cbase = clouds + (size_t)b*4*NPTS;
        sg[t][0] = cbase[pi]        - g_kp_xyz[kp*3+0];
        sg[t][1] = cbase[NPTS+pi]   - g_kp_xyz[kp*3+1];
        sg[t][2] = cbase[2*NPTS+pi] - g_kp_xyz[kp*3+2];
        sg[t][3] = cbase[3*NPTS+pi];
    }
    __syncthreads();

    for (int e = t; e < 128*32; e += 256) {
        int j = e & 31, i = e >> 5;
        float v = 0.f;
        if (j < cb2) {
            float a = __fmul_rn(sg[j][0], w1b[i]);
            a = fmaf(sg[j][1], w1b[128+i], a);
            a = fmaf(sg[j][2], w1b[256+i], a);
            a = fmaf(sg[j][3], w1b[384+i], a);
            v = fmaxf(a, 0.f);
        }
        h1bt[i*32 + j] = v;
    }
    for (int e = t; e < 128*16; e += 256) {
        int j = e & 15, i = e >> 4;
        float v = 0.f;
        if (j < ca) {
            float a = __fmul_rn(sg[j][0], w1a[i]);
            a = fmaf(sg[j][1], w1a[128+i], a);
            a = fmaf(sg[j][2], w1a[256+i], a);
            a = fmaf(sg[j][3], w1a[384+i], a);
            v = fmaxf(a, 0.f);
        }
        h1at[i*16 + j] = v;
    }
    __syncthreads();

    float accb[32];
    #pragma unroll
    for (int j = 0; j < 32; j++) accb[j] = 0.f;
    for (int i = 0; i < 128; i++) {
        float wvl = __ldg(&w2b[i*256 + t]);
        const float4* hr = reinterpret_cast<const float4*>(h1bt + i*32);
        #pragma unroll
        for (int j4 = 0; j4 < 8; j4++) {
            float4 h = hr[j4];
            accb[j4*4+0] = fmaf(h.x, wvl, accb[j4*4+0]);
            accb[j4*4+1] = fmaf(h.y, wvl, accb[j4*4+1]);
            accb[j4*4+2] = fmaf(h.z, wvl, accb[j4*4+2]);
            accb[j4*4+3] = fmaf(h.w, wvl, accb[j4*4+3]);
        }
    }
    float bestb = 0.f;
    #pragma unroll
    for (int j = 0; j < 32; j++) bestb = fmaxf(bestb, accb[j]);

    float acca[16];
    #pragma unroll
    for (int j = 0; j < 16; j++) acca[j] = 0.f;
    for (int i = 0; i < 128; i++) {
        float wvl = __ldg(&w2a[i*256 + t]);
        const float4* hr = reinterpret_cast<const float4*>(h1at + i*16);
        #pragma unroll
        for (int j4 = 0; j4 < 4; j4++) {
            float4 h = hr[j4];
            acca[j4*4+0] = fmaf(h.x, wvl, acca[j4*4+0]);
            acca[j4*4+1] = fmaf(h.y, wvl, acca[j4*4+1]);
            acca[j4*4+2] = fmaf(h.z, wvl, acca[j4*4+2]);
            acca[j4*4+3] = fmaf(h.w, wvl, acca[j4*4+3]);
        }
    }
    float besta = 0.f;
    #pragma unroll
    for (int j = 0; j < 16; j++) besta = fmaxf(besta, acca[j]);

    g_pooled[kp*512 + t]       = besta;
    g_pooled[kp*512 + 256 + t] = bestb;
}

// ============ K5: fusion + output (16 kp per block) ============
__global__ __launch_bounds__(128) void fuse_kernel(const float* __restrict__ wf,
                                                   float* __restrict__ out) {
    int kp0 = blockIdx.x * 16;
    __shared__ float sp[512*16];
    int t = threadIdx.x;
    for (int e = t; e < 512*16; e += 128) {
        int c = e & 511, q = e >> 9;
        sp[c*16 + q] = g_pooled[(size_t)(kp0 + q)*512 + c];
    }
    __syncthreads();
    float acc[16];
    #pragma unroll
    for (int q = 0; q < 16; q++) acc[q] = 0.f;
    for (int c = 0; c < 512; c++) {
        float wvl = __ldg(&wf[c*128 + t]);
        const float4* pr = reinterpret_cast<const float4*>(sp + c*16);
        #pragma unroll
        for (int q4 = 0; q4 < 4; q4++) {
            float4 p = pr[q4];
            acc[q4*4+0] = fmaf(p.x, wvl, acc[q4*4+0]);
            acc[q4*4+1] = fmaf(p.y, wvl, acc[q4*4+1]);
            acc[q4*4+2] = fmaf(p.z, wvl, acc[q4*4+2]);
            acc[q4*4+3] = fmaf(p.w, wvl, acc[q4*4+3]);
        }
    }
    #pragma unroll
    for (int q = 0; q < 16; q++)
        out[(size_t)(kp0+q)*131 + 3 + t] = fmaxf(acc[q], 0.f);
    if (t < 48) {
        int q = t / 3, comp = t % 3;
        out[(size_t)(kp0+q)*131 + comp] = g_kp_xyz[(kp0+q)*3 + comp];
    }
}

extern "C" void kernel_launch(void* const* d_in, const int* in_sizes, int n_in,
                              void* d_out, int out_size) {
    const float* clouds = (const float*)d_in[0];
    const float* w1a    = (const float*)d_in[1];
    const float* w2a    = (const float*)d_in[2];
    const float* w1b    = (const float*)d_in[3];
    const float* w2b    = (const float*)d_in[4];
    const float* wf     = (const float*)d_in[5];
    float* out = (float*)d_out;

    // sxT+syT+szT (196608) + spermT (32768) + hist (2048) + warp caches (384) + misc (64)
    int fps_smem = 3*NPTS*4 + NPTS*2 + NCELLS*4 + 384 + 64;
    cudaFuncSetAttribute(fps_kernel, cudaFuncAttributeMaxDynamicSharedMemorySize, fps_smem);
    fps_kernel<<<BATCH, NTHR, fps_smem>>>(clouds);

    dim3 g2(NKP/16, BATCH);
    ballq_kernel<<<g2, 128>>>(clouds);
    select_kernel<<<TOTKP/8, 256>>>();
    mlp_kernel<<<TOTKP, 256>>>(clouds, w1a, w2a, w1b, w2b);
    fuse_kernel<<<TOTKP/16, 128>>>(wf, out);
}

// round 6
// speedup vs baseline: 1.9485x; 1.1161x over previous
#include <cuda_runtime.h>

#define BATCH 2
#define NPTS  16384
#define NKP   4096
#define TOTKP (BATCH*NKP)
#define CCAP  384
#define R2A_CONST ((float)(0.8*0.8))
#define R2B_CONST ((float)(1.6*1.6))
#define NTHR  1024
#define PPT   16
#define NCELLS 512

__device__ float g_kp_xyz[TOTKP*3];
__device__ int   g_kp_sorted[TOTKP];
__device__ float4 g_sorted4[BATCH*NPTS];
__device__ int   g_cell_end[BATCH*NCELLS];
__device__ float g_grid[BATCH*8];
__device__ float g_cand_d[TOTKP*CCAP];
__device__ int   g_cand_i[TOTKP*CCAP];
__device__ int   g_cand_cnt[TOTKP];
__device__ int   g_nbr[TOTKP*32];
__device__ int   g_cnt_a[TOTKP];
__device__ int   g_cnt_b[TOTKP];
__device__ float g_pooled[TOTKP*512];

__device__ __forceinline__ float dist2_ref(float dx, float dy, float dz) {
    return __fadd_rn(__fadd_rn(__fmul_rn(dx,dx), __fmul_rn(dy,dy)), __fmul_rn(dz,dz));
}
__device__ __forceinline__ unsigned fenc(float f) {   // monotone for f >= 0
    return __float_as_uint(f) | 0x80000000u;
}
__device__ __forceinline__ unsigned fenc_s(float f) { // full monotone encode
    unsigned u = __float_as_uint(f);
    return (u & 0x80000000u) ? ~u : (u | 0x80000000u);
}
__device__ __forceinline__ float fdec_s(unsigned u) {
    return __uint_as_float((u & 0x80000000u) ? (u & 0x7fffffffu) : ~u);
}
__device__ __forceinline__ int mort4(int v) {
    v = (v | (v << 2)) & 0x33;
    v = (v | (v << 1)) & 0x55;
    return v;
}

// ============ K1: FPS, bucket-skip + single-barrier atomic merge ============
extern __shared__ unsigned char dsm[];

__global__ __launch_bounds__(NTHR,1) void fps_kernel(const float* __restrict__ clouds) {
    int b = blockIdx.x;
    float* sxT = (float*)dsm;
    float* syT = sxT + NPTS;
    float* szT = syT + NPTS;
    unsigned short* spermT = (unsigned short*)(szT + NPTS);
    unsigned int*   hist   = (unsigned int*)(spermT + NPTS);
    unsigned long long* slots = (unsigned long long*)(hist + NCELLS);  // 8B aligned
    unsigned int* s_bb = (unsigned int*)(slots + 3);   // [0..5] bbox encoded

    const float* cb = clouds + (size_t)b*4*NPTS;
    int t = threadIdx.x, lane = t & 31;

    if (t < 3)            s_bb[t]   = 0xFFFFFFFFu;
    else if (t < 6)       s_bb[t]   = 0u;
    if (t < 2)            slots[t]  = 0ull;
    for (int c = t; c < NCELLS; c += NTHR) hist[c] = 0;
    __syncthreads();
    {
        float mnx=1e30f,mny=1e30f,mnz=1e30f,mxx=-1e30f,mxy=-1e30f,mxz=-1e30f;
        for (int j = 0; j < PPT; j++) {
            int i = t + j*NTHR;
            float x = cb[i], y = cb[NPTS+i], z = cb[2*NPTS+i];
            mnx = fminf(mnx,x); mny = fminf(mny,y); mnz = fminf(mnz,z);
            mxx = fmaxf(mxx,x); mxy = fmaxf(mxy,y); mxz = fmaxf(mxz,z);
        }
        #pragma unroll
        for (int off = 16; off > 0; off >>= 1) {
            mnx = fminf(mnx, __shfl_down_sync(0xffffffffu, mnx, off));
            mny = fminf(mny, __shfl_down_sync(0xffffffffu, mny, off));
            mnz = fminf(mnz, __shfl_down_sync(0xffffffffu, mnz, off));
            mxx = fmaxf(mxx, __shfl_down_sync(0xffffffffu, mxx, off));
            mxy = fmaxf(mxy, __shfl_down_sync(0xffffffffu, mxy, off));
            mxz = fmaxf(mxz, __shfl_down_sync(0xffffffffu, mxz, off));
        }
        if (lane == 0) {
            atomicMin(&s_bb[0], fenc_s(mnx));
            atomicMin(&s_bb[1], fenc_s(mny));
            atomicMin(&s_bb[2], fenc_s(mnz));
            atomicMax(&s_bb[3], fenc_s(mxx));
            atomicMax(&s_bb[4], fenc_s(mxy));
            atomicMax(&s_bb[5], fenc_s(mxz));
        }
    }
    __syncthreads();
    float gminx = fdec_s(s_bb[0]), gminy = fdec_s(s_bb[1]), gminz = fdec_s(s_bb[2]);
    float grx = 16.0f / fmaxf(fdec_s(s_bb[3]) - gminx, 1e-9f);
    float gry = 16.0f / fmaxf(fdec_s(s_bb[4]) - gminy, 1e-9f);
    float grz = 2.0f  / fmaxf(fdec_s(s_bb[5]) - gminz, 1e-9f);

    for (int j = 0; j < PPT; j++) {
        int i = t + j*NTHR;
        int cx = min(15, (int)((cb[i]        - gminx) * grx));
        int cy = min(15, (int)((cb[NPTS+i]   - gminy) * gry));
        int cz = min(1,  (int)((cb[2*NPTS+i] - gminz) * grz));
        int cell = (((mort4(cy) << 1) | mort4(cx)) << 1) | cz;
        atomicAdd(&hist[cell], 1u);
    }
    __syncthreads();
    for (int off = 1; off < NCELLS; off <<= 1) {
        unsigned v = 0;
        if (t < NCELLS && t >= off) v = hist[t-off];
        __syncthreads();
        if (t < NCELLS) hist[t] += v;
        __syncthreads();
    }
    {
        unsigned v = (t == 0) ? 0u : ((t < NCELLS) ? hist[t-1] : 0u);
        __syncthreads();
        if (t < NCELLS) hist[t] = v;
        __syncthreads();
    }
    for (int j = 0; j < PPT; j++) {
        int i = t + j*NTHR;
        float x = cb[i], y = cb[NPTS+i], z = cb[2*NPTS+i];
        int cx = min(15, (int)((x - gminx) * grx));
        int cy = min(15, (int)((y - gminy) * gry));
        int cz = min(1,  (int)((z - gminz) * grz));
        int cell = (((mort4(cy) << 1) | mort4(cx)) << 1) | cz;
        int p = (int)atomicAdd(&hist[cell], 1u);
        int phys = (p & 15)*NTHR + (p >> 4);
        sxT[phys] = x; syT[phys] = y; szT[phys] = z;
        spermT[phys] = (unsigned short)i;
        if (i == 0) slots[2] = (unsigned long long)p;  // iter0 winner = orig point 0
    }
    __syncthreads();

    float dmin[PPT];
    float bxmin=1e30f, bymin=1e30f, bzmin=1e30f, bxmax=-1e30f, bymax=-1e30f, bzmax=-1e30f;
    #pragma unroll
    for (int j = 0; j < PPT; j++) {
        dmin[j] = 1e10f;
        float x = sxT[j*NTHR + t], y = syT[j*NTHR + t], z = szT[j*NTHR + t];
        bxmin = fminf(bxmin,x); bymin = fminf(bymin,y); bzmin = fminf(bzmin,z);
        bxmax = fmaxf(bxmax,x); bymax = fmaxf(bymax,y); bzmax = fmaxf(bzmax,z);
    }
    float bestv = 1e10f; int bestorig = 0x3fff; int bestsorted = t*PPT;
    unsigned long long wkey = 0ull;
    int cur = 0, prev = 2, nxt = 1;

    for (int it = 0; it < NKP; ++it) {
        unsigned long long lk = slots[prev];
        int last = (int)(lk & 0x3fffull);
        if (t == 0) g_kp_sorted[b*NKP + it] = last;
        if (it == NKP-1) break;

        int lphys = (last & 15)*NTHR + (last >> 4);
        float lx = sxT[lphys], ly = syT[lphys], lz = szT[lphys];

        float dx = fmaxf(fmaxf(bxmin - lx, lx - bxmax), 0.f);
        float dy = fmaxf(fmaxf(bymin - ly, ly - bymax), 0.f);
        float dz = fmaxf(fmaxf(bzmin - lz, lz - bzmax), 0.f);
        float d2b = fmaf(dx, dx, fmaf(dy, dy, dz*dz));
        bool need = (d2b * 0.99999f) < bestv;

        if (need) {
            float bv = -1.f; int bo = 0x3fff, bs = t*PPT;
            #pragma unroll
            for (int j = 0; j < PPT; j++) {
                int phys = j*NTHR + t;
                float d  = dist2_ref(sxT[phys]-lx, syT[phys]-ly, szT[phys]-lz);
                float nd = fminf(dmin[j], d);
                dmin[j] = nd;
                int o = (int)spermT[phys];
                if (nd > bv || (nd == bv && o < bo)) { bv = nd; bo = o; bs = t*PPT + j; }
            }
            bestv = bv; bestorig = bo; bestsorted = bs;
        }
        unsigned m = __ballot_sync(0xffffffffu, need);
        if (m) {  // recompute warp key: max d, then lowest orig, carry sorted pos
            unsigned fv   = fenc(bestv);
            unsigned wmax = __reduce_max_sync(0xffffffffu, fv);
            unsigned lo28 = (fv == wmax) ? ((unsigned)(0x3fff - bestorig) << 14) | (unsigned)bestsorted : 0u;
            unsigned lmax = __reduce_max_sync(0xffffffffu, lo28);
            wkey = ((unsigned long long)wmax << 28) | (unsigned long long)lmax;
        }
        if (lane == 0) atomicMax(&slots[cur], wkey);
        if (t == 0) slots[nxt] = 0ull;   // last read two barriers ago; safe to reset
        __syncthreads();
        int tmp = prev; prev = cur; cur = nxt; nxt = tmp;
    }
    __syncthreads();

    for (int k = t; k < NKP; k += NTHR) {
        int p = g_kp_sorted[b*NKP + k];
        int phys = (p & 15)*NTHR + (p >> 4);
        g_kp_xyz[(b*NKP+k)*3+0] = sxT[phys];
        g_kp_xyz[(b*NKP+k)*3+1] = syT[phys];
        g_kp_xyz[(b*NKP+k)*3+2] = szT[phys];
    }
    // export sorted structure for cell-pruned ball query
    for (int p = t; p < NPTS; p += NTHR) {
        int phys = (p & 15)*NTHR + (p >> 4);
        g_sorted4[b*NPTS + p] = make_float4(sxT[phys], syT[phys], szT[phys],
                                            __int_as_float((int)spermT[phys]));
    }
    for (int c = t; c < NCELLS; c += NTHR) g_cell_end[b*NCELLS + c] = (int)hist[c];
    if (t == 0) {
        g_grid[b*8+0] = gminx; g_grid[b*8+1] = gminy; g_grid[b*8+2] = gminz;
        g_grid[b*8+3] = grx;   g_grid[b*8+4] = gry;   g_grid[b*8+5] = grz;
    }
}

// ============ K2: cell-pruned ball query (one warp per keypoint) ============
// uniform-trip loops: every lane executes the same number of iterations, so
// all lanes reach every __ballot_sync (fixes R5 divergent-collective hang)
__global__ __launch_bounds__(256) void ballq_kernel() {
    int kp = blockIdx.x * 8 + (threadIdx.x >> 5);
    int b = kp >> 12, lane = threadIdx.x & 31;
    float kx = g_kp_xyz[kp*3+0], ky = g_kp_xyz[kp*3+1], kz = g_kp_xyz[kp*3+2];
    float gminx = g_grid[b*8+0], gminy = g_grid[b*8+1], gminz = g_grid[b*8+2];
    float grx = g_grid[b*8+3], gry = g_grid[b*8+4], grz = g_grid[b*8+5];
    const float4* sp4 = g_sorted4 + b*NPTS;
    const int* cend = g_cell_end + b*NCELLS;

    const float R = 1.6005f;   // pads float-rounding at the exact-radius boundary
    int cx0 = max(0, min(15, (int)floorf((kx - R - gminx) * grx)));
    int cx1 = max(0, min(15, (int)floorf((kx + R - gminx) * grx)));
    int cy0 = max(0, min(15, (int)floorf((ky - R - gminy) * gry)));
    int cy1 = max(0, min(15, (int)floorf((ky + R - gminy) * gry)));
    int cz0 = max(0, min(1,  (int)floorf((kz - R - gminz) * grz)));
    int cz1 = max(0, min(1,  (int)floorf((kz + R - gminz) * grz)));

    int cnt = 0;
    unsigned lmask = (1u << lane) - 1u;
    for (int cy = cy0; cy <= cy1; cy++) {
        for (int cx = cx0; cx <= cx1; cx++) {
            int base = ((mort4(cy) << 1) | mort4(cx)) << 1;
            int c0 = base | cz0, c1 = base | cz1;   // contiguous in sorted order
            int pstart = (c0 == 0) ? 0 : cend[c0-1];
            int pend = cend[c1];
            for (int p0 = pstart; p0 < pend; p0 += 32) {   // uniform trip count
                int p = p0 + lane;
                bool in = p < pend;
                float4 P = in ? sp4[p] : make_float4(1e30f, 1e30f, 1e30f, 0.f);
                float d2 = dist2_ref(kx - P.x, ky - P.y, kz - P.z);
                bool hit = in && (d2 < R2B_CONST);
                unsigned m = __ballot_sync(0xffffffffu, hit);
                if (hit) {
                    int pos = cnt + __popc(m & lmask);
                    if (pos < CCAP) {
                        g_cand_d[kp*CCAP + pos] = d2;
                        g_cand_i[kp*CCAP + pos] = __float_as_int(P.w);
                    }
                }
                cnt += __popc(m);
            }
        }
    }
    if (lane == 0) g_cand_cnt[kp] = (cnt < CCAP) ? cnt : CCAP;
}

// ============ K3: rank candidates (one warp per keypoint) ============
__global__ __launch_bounds__(256) void select_kernel() {
    __shared__ float sd[8*CCAP];
    __shared__ int   si[8*CCAP];
    int w = threadIdx.x >> 5, lane = threadIdx.x & 31;
    int kp = blockIdx.x * 8 + w;
    float* swd = sd + w*CCAP; int* swi = si + w*CCAP;
    int n = g_cand_cnt[kp];
    for (int c = lane; c < n; c += 32) {
        swd[c] = g_cand_d[kp*CCAP + c];
        swi[c] = g_cand_i[kp*CCAP + c];
    }
    __syncwarp();
    int na = 0;
    for (int c = lane; c < n; c += 32) {
        float dc = swd[c];
        int oc = swi[c];
        int rank = 0;
        for (int c2 = 0; c2 < n; c2++) {
            float dv = swd[c2];
            rank += (dv < dc) || (dv == dc && swi[c2] < oc);  // ties -> lower orig idx
        }
        if (rank < 32) g_nbr[kp*32 + rank] = oc;
        if (rank < 16 && dc < R2A_CONST) na++;
    }
    #pragma unroll
    for (int off = 16; off > 0; off >>= 1) na += __shfl_down_sync(0xffffffffu, na, off);
    if (lane == 0) {
        g_cnt_a[kp] = na;
        g_cnt_b[kp] = (n < 32) ? n : 32;
    }
}

// ============ K4: PointNet MLP + max pool (one block per keypoint) ============
__global__ __launch_bounds__(256) void mlp_kernel(const float* __restrict__ clouds,
                                                  const float* __restrict__ w1a,
                                                  const float* __restrict__ w2a,
                                                  const float* __restrict__ w1b,
                                                  const float* __restrict__ w2b) {
    int kp = blockIdx.x;
    int b  = kp >> 12;
    __shared__ float sg[32][5];
    __shared__ float h1bt[128*32];
    __shared__ float h1at[128*16];
    __shared__ int   s_ca, s_cb;
    int t = threadIdx.x;
    if (t == 0) { s_ca = g_cnt_a[kp]; s_cb = g_cnt_b[kp]; }
    __syncthreads();
    int ca = s_ca, cb2 = s_cb;

    if (t < 32 && t < cb2) {
        int pi = g_nbr[kp*32 + t];
        const float* cbase = clouds + (size_t)b*4*NPTS;
        sg[t][0] = cbase[pi]        - g_kp_xyz[kp*3+0];
        sg[t][1] = cbase[NPTS+pi]   - g_kp_xyz[kp*3+1];
        sg[t][2] = cbase[2*NPTS+pi] - g_kp_xyz[kp*3+2];
        sg[t][3] = cbase[3*NPTS+pi];
    }
    __syncthreads();

    for (int e = t; e < 128*32; e += 256) {
        int j = e & 31, i = e >> 5;
        float v = 0.f;
        if (j < cb2) {
            float a = __fmul_rn(sg[j][0], w1b[i]);
            a = fmaf(sg[j][1], w1b[128+i], a);
            a = fmaf(sg[j][2], w1b[256+i], a);
            a = fmaf(sg[j][3], w1b[384+i], a);
            v = fmaxf(a, 0.f);
        }
        h1bt[i*32 + j] = v;
    }
    for (int e = t; e < 128*16; e += 256) {
        int j = e & 15, i = e >> 4;
        float v = 0.f;
        if (j < ca) {
            float a = __fmul_rn(sg[j][0], w1a[i]);
            a = fmaf(sg[j][1], w1a[128+i], a);
            a = fmaf(sg[j][2], w1a[256+i], a);
            a = fmaf(sg[j][3], w1a[384+i], a);
            v = fmaxf(a, 0.f);
        }
        h1at[i*16 + j] = v;
    }
    __syncthreads();

    float accb[32];
    #pragma unroll
    for (int j = 0; j < 32; j++) accb[j] = 0.f;
    for (int i = 0; i < 128; i++) {
        float wvl = __ldg(&w2b[i*256 + t]);
        const float4* hr = reinterpret_cast<const float4*>(h1bt + i*32);
        #pragma unroll
        for (int j4 = 0; j4 < 8; j4++) {
            float4 h = hr[j4];
            accb[j4*4+0] = fmaf(h.x, wvl, accb[j4*4+0]);
            accb[j4*4+1] = fmaf(h.y, wvl, accb[j4*4+1]);
            accb[j4*4+2] = fmaf(h.z, wvl, accb[j4*4+2]);
            accb[j4*4+3] = fmaf(h.w, wvl, accb[j4*4+3]);
        }
    }
    float bestb = 0.f;
    #pragma unroll
    for (int j = 0; j < 32; j++) bestb = fmaxf(bestb, accb[j]);

    float acca[16];
    #pragma unroll
    for (int j = 0; j < 16; j++) acca[j] = 0.f;
    for (int i = 0; i < 128; i++) {
        float wvl = __ldg(&w2a[i*256 + t]);
        const float4* hr = reinterpret_cast<const float4*>(h1at + i*16);
        #pragma unroll
        for (int j4 = 0; j4 < 4; j4++) {
            float4 h = hr[j4];
            acca[j4*4+0] = fmaf(h.x, wvl, acca[j4*4+0]);
            acca[j4*4+1] = fmaf(h.y, wvl, acca[j4*4+1]);
            acca[j4*4+2] = fmaf(h.z, wvl, acca[j4*4+2]);
            acca[j4*4+3] = fmaf(h.w, wvl, acca[j4*4+3]);
        }
    }
    float besta = 0.f;
    #pragma unroll
    for (int j = 0; j < 16; j++) besta = fmaxf(besta, acca[j]);

    g_pooled[kp*512 + t]       = besta;
    g_pooled[kp*512 + 256 + t] = bestb;
}

// ============ K5: fusion + output (16 kp per block) ============
__global__ __launch_bounds__(128) void fuse_kernel(const float* __restrict__ wf,
                                                   float* __restrict__ out) {
    int kp0 = blockIdx.x * 16;
    __shared__ float sp[512*16];
    int t = threadIdx.x;
    for (int e = t; e < 512*16; e += 128) {
        int c = e & 511, q = e >> 9;
        sp[c*16 + q] = g_pooled[(size_t)(kp0 + q)*512 + c];
    }
    __syncthreads();
    float acc[16];
    #pragma unroll
    for (int q = 0; q < 16; q++) acc[q] = 0.f;
    for (int c = 0; c < 512; c++) {
        float wvl = __ldg(&wf[c*128 + t]);
        const float4* pr = reinterpret_cast<const float4*>(sp + c*16);
        #pragma unroll
        for (int q4 = 0; q4 < 4; q4++) {
            float4 p = pr[q4];
            acc[q4*4+0] = fmaf(p.x, wvl, acc[q4*4+0]);
            acc[q4*4+1] = fmaf(p.y, wvl, acc[q4*4+1]);
            acc[q4*4+2] = fmaf(p.z, wvl, acc[q4*4+2]);
            acc[q4*4+3] = fmaf(p.w, wvl, acc[q4*4+3]);
        }
    }
    #pragma unroll
    for (int q = 0; q < 16; q++)
        out[(size_t)(kp0+q)*131 + 3 + t] = fmaxf(acc[q], 0.f);
    if (t < 48) {
        int q = t / 3, comp = t % 3;
        out[(size_t)(kp0+q)*131 + comp] = g_kp_xyz[(kp0+q)*3 + comp];
    }
}

extern "C" void kernel_launch(void* const* d_in, const int* in_sizes, int n_in,
                              void* d_out, int out_size) {
    const float* clouds = (const float*)d_in[0];
    const float* w1a    = (const float*)d_in[1];
    const float* w2a    = (const float*)d_in[2];
    const float* w1b    = (const float*)d_in[3];
    const float* w2b    = (const float*)d_in[4];
    const float* wf     = (const float*)d_in[5];
    float* out = (float*)d_out;

    int fps_smem = 3*NPTS*4 + NPTS*2 + NCELLS*4 + 24 + 24 + 16;
    cudaFuncSetAttribute(fps_kernel, cudaFuncAttributeMaxDynamicSharedMemorySize, fps_smem);
    fps_kernel<<<BATCH, NTHR, fps_smem>>>(clouds);

    ballq_kernel<<<TOTKP/8, 256>>>();
    select_kernel<<<TOTKP/8, 256>>>();
    mlp_kernel<<<TOTKP, 256>>>(clouds, w1a, w2a, w1b, w2b);
    fuse_kernel<<<TOTKP/16, 128>>>(wf, out);
}

// round 7
// speedup vs baseline: 2.0028x; 1.0278x over previous
#include <cuda_runtime.h>

#define BATCH 2
#define NPTS  16384
#define NKP   4096
#define TOTKP (BATCH*NKP)
#define CCAP  384
#define R2A_CONST ((float)(0.8*0.8))
#define R2B_CONST ((float)(1.6*1.6))
#define NTHR  1024
#define PPT   16
#define NCELLS 512

__device__ float g_kp_xyz[TOTKP*3];
__device__ int   g_kp_sorted[TOTKP];
__device__ float4 g_sorted4[BATCH*NPTS];
__device__ int   g_cell_end[BATCH*NCELLS];
__device__ float g_grid[BATCH*8];
__device__ float g_cand_d[TOTKP*CCAP];
__device__ int   g_cand_i[TOTKP*CCAP];
__device__ int   g_cand_cnt[TOTKP];
__device__ int   g_nbr[TOTKP*32];
__device__ int   g_cnt_a[TOTKP];
__device__ int   g_cnt_b[TOTKP];
__device__ float g_pooled[TOTKP*512];

__device__ __forceinline__ float dist2_ref(float dx, float dy, float dz) {
    return __fadd_rn(__fadd_rn(__fmul_rn(dx,dx), __fmul_rn(dy,dy)), __fmul_rn(dz,dz));
}
__device__ __forceinline__ unsigned fenc(float f) {   // monotone for f >= 0
    return __float_as_uint(f) | 0x80000000u;
}
__device__ __forceinline__ unsigned fenc_s(float f) { // full monotone encode
    unsigned u = __float_as_uint(f);
    return (u & 0x80000000u) ? ~u : (u | 0x80000000u);
}
__device__ __forceinline__ float fdec_s(unsigned u) {
    return __uint_as_float((u & 0x80000000u) ? (u & 0x7fffffffu) : ~u);
}
__device__ __forceinline__ int mort4(int v) {
    v = (v | (v << 2)) & 0x33;
    v = (v | (v << 1)) & 0x55;
    return v;
}
// packed f32x2 FMA: acc = h2 * w2 + acc  (two independent IEEE fp32 FMAs)
__device__ __forceinline__ void ffma2(unsigned long long& acc, unsigned long long h2,
                                      unsigned long long w2) {
    asm("fma.rn.f32x2 %0, %1, %2, %0;" : "+l"(acc) : "l"(h2), "l"(w2));
}
__device__ __forceinline__ unsigned long long dup2(float w) {
    unsigned long long r;
    asm("mov.b64 %0, {%1, %1};" : "=l"(r) : "r"(__float_as_uint(w)));
    return r;
}
__device__ __forceinline__ float pairmax(unsigned long long a) {
    unsigned lo, hi;
    asm("mov.b64 {%0, %1}, %2;" : "=r"(lo), "=r"(hi) : "l"(a));
    return fmaxf(__uint_as_float(lo), __uint_as_float(hi));
}

// ============ K1: FPS, bucket-skip + predicated atomic merge ============
extern __shared__ unsigned char dsm[];

__global__ __launch_bounds__(NTHR,1) void fps_kernel(const float* __restrict__ clouds) {
    int b = blockIdx.x;
    float* sxT = (float*)dsm;
    float* syT = sxT + NPTS;
    float* szT = syT + NPTS;
    unsigned short* spermT = (unsigned short*)(szT + NPTS);
    unsigned int*   hist   = (unsigned int*)(spermT + NPTS);
    unsigned long long* slots = (unsigned long long*)(hist + NCELLS);  // 8B aligned
    unsigned int* s_bb = (unsigned int*)(slots + 3);   // [0..5] bbox encoded

    const float* cb = clouds + (size_t)b*4*NPTS;
    int t = threadIdx.x, lane = t & 31;

    if (t < 3)            s_bb[t]   = 0xFFFFFFFFu;
    else if (t < 6)       s_bb[t]   = 0u;
    if (t < 2)            slots[t]  = 0ull;
    for (int c = t; c < NCELLS; c += NTHR) hist[c] = 0;
    __syncthreads();
    {
        float mnx=1e30f,mny=1e30f,mnz=1e30f,mxx=-1e30f,mxy=-1e30f,mxz=-1e30f;
        for (int j = 0; j < PPT; j++) {
            int i = t + j*NTHR;
            float x = cb[i], y = cb[NPTS+i], z = cb[2*NPTS+i];
            mnx = fminf(mnx,x); mny = fminf(mny,y); mnz = fminf(mnz,z);
            mxx = fmaxf(mxx,x); mxy = fmaxf(mxy,y); mxz = fmaxf(mxz,z);
        }
        #pragma unroll
        for (int off = 16; off > 0; off >>= 1) {
            mnx = fminf(mnx, __shfl_down_sync(0xffffffffu, mnx, off));
            mny = fminf(mny, __shfl_down_sync(0xffffffffu, mny, off));
            mnz = fminf(mnz, __shfl_down_sync(0xffffffffu, mnz, off));
            mxx = fmaxf(mxx, __shfl_down_sync(0xffffffffu, mxx, off));
            mxy = fmaxf(mxy, __shfl_down_sync(0xffffffffu, mxy, off));
            mxz = fmaxf(mxz, __shfl_down_sync(0xffffffffu, mxz, off));
        }
        if (lane == 0) {
            atomicMin(&s_bb[0], fenc_s(mnx));
            atomicMin(&s_bb[1], fenc_s(mny));
            atomicMin(&s_bb[2], fenc_s(mnz));
            atomicMax(&s_bb[3], fenc_s(mxx));
            atomicMax(&s_bb[4], fenc_s(mxy));
            atomicMax(&s_bb[5], fenc_s(mxz));
        }
    }
    __syncthreads();
    float gminx = fdec_s(s_bb[0]), gminy = fdec_s(s_bb[1]), gminz = fdec_s(s_bb[2]);
    float grx = 16.0f / fmaxf(fdec_s(s_bb[3]) - gminx, 1e-9f);
    float gry = 16.0f / fmaxf(fdec_s(s_bb[4]) - gminy, 1e-9f);
    float grz = 2.0f  / fmaxf(fdec_s(s_bb[5]) - gminz, 1e-9f);

    for (int j = 0; j < PPT; j++) {
        int i = t + j*NTHR;
        int cx = min(15, (int)((cb[i]        - gminx) * grx));
        int cy = min(15, (int)((cb[NPTS+i]   - gminy) * gry));
        int cz = min(1,  (int)((cb[2*NPTS+i] - gminz) * grz));
        int cell = (((mort4(cy) << 1) | mort4(cx)) << 1) | cz;
        atomicAdd(&hist[cell], 1u);
    }
    __syncthreads();
    for (int off = 1; off < NCELLS; off <<= 1) {
        unsigned v = 0;
        if (t < NCELLS && t >= off) v = hist[t-off];
        __syncthreads();
        if (t < NCELLS) hist[t] += v;
        __syncthreads();
    }
    {
        unsigned v = (t == 0) ? 0u : ((t < NCELLS) ? hist[t-1] : 0u);
        __syncthreads();
        if (t < NCELLS) hist[t] = v;
        __syncthreads();
    }
    for (int j = 0; j < PPT; j++) {
        int i = t + j*NTHR;
        float x = cb[i], y = cb[NPTS+i], z = cb[2*NPTS+i];
        int cx = min(15, (int)((x - gminx) * grx));
        int cy = min(15, (int)((y - gminy) * gry));
        int cz = min(1,  (int)((z - gminz) * grz));
        int cell = (((mort4(cy) << 1) | mort4(cx)) << 1) | cz;
        int p = (int)atomicAdd(&hist[cell], 1u);
        int phys = (p & 15)*NTHR + (p >> 4);
        sxT[phys] = x; syT[phys] = y; szT[phys] = z;
        spermT[phys] = (unsigned short)i;
        if (i == 0) slots[2] = (unsigned long long)p;  // iter0 winner = orig point 0
    }
    __syncthreads();

    float dmin[PPT];
    float bxmin=1e30f, bymin=1e30f, bzmin=1e30f, bxmax=-1e30f, bymax=-1e30f, bzmax=-1e30f;
    #pragma unroll
    for (int j = 0; j < PPT; j++) {
        dmin[j] = 1e10f;
        float x = sxT[j*NTHR + t], y = syT[j*NTHR + t], z = szT[j*NTHR + t];
        bxmin = fminf(bxmin,x); bymin = fminf(bymin,y); bzmin = fminf(bzmin,z);
        bxmax = fmaxf(bxmax,x); bymax = fmaxf(bymax,y); bzmax = fmaxf(bzmax,z);
    }
    float bestv = 1e10f; int bestorig = 0x3fff; int bestsorted = t*PPT;
    unsigned long long wkey = 0ull;
    int cur = 0, prev = 2, nxt = 1;

    for (int it = 0; it < NKP; ++it) {
        unsigned long long lk = slots[prev];
        int last = (int)(lk & 0x3fffull);
        if (t == 0) g_kp_sorted[b*NKP + it] = last;
        if (it == NKP-1) break;

        int lphys = (last & 15)*NTHR + (last >> 4);
        float lx = sxT[lphys], ly = syT[lphys], lz = szT[lphys];

        float dx = fmaxf(fmaxf(bxmin - lx, lx - bxmax), 0.f);
        float dy = fmaxf(fmaxf(bymin - ly, ly - bymax), 0.f);
        float dz = fmaxf(fmaxf(bzmin - lz, lz - bzmax), 0.f);
        float d2b = fmaf(dx, dx, fmaf(dy, dy, dz*dz));
        bool need = (d2b * 0.99999f) < bestv;

        if (need) {
            float bv = -1.f; int bo = 0x3fff, bs = t*PPT;
            #pragma unroll
            for (int j = 0; j < PPT; j++) {
                int phys = j*NTHR + t;
                float d  = dist2_ref(sxT[phys]-lx, syT[phys]-ly, szT[phys]-lz);
                float nd = fminf(dmin[j], d);
                dmin[j] = nd;
                int o = (int)spermT[phys];
                if (nd > bv || (nd == bv && o < bo)) { bv = nd; bo = o; bs = t*PPT + j; }
            }
            bestv = bv; bestorig = bo; bestsorted = bs;
        }
        unsigned m = __ballot_sync(0xffffffffu, need);
        if (m) {  // recompute warp key: max d, then lowest orig, carry sorted pos
            unsigned fv   = fenc(bestv);
            unsigned wmax = __reduce_max_sync(0xffffffffu, fv);
            unsigned lo28 = (fv == wmax) ? ((unsigned)(0x3fff - bestorig) << 14) | (unsigned)bestsorted : 0u;
            unsigned lmax = __reduce_max_sync(0xffffffffu, lo28);
            wkey = ((unsigned long long)wmax << 28) | (unsigned long long)lmax;
        }
        if (lane == 0) {
            // predicated merge: skip the (serializing) single-address ATOMS when
            // our cached key is provably dominated; stale reads are conservative
            unsigned long long seen = slots[cur];
            if (wkey > seen) atomicMax(&slots[cur], wkey);
        }
        if (t == 0) slots[nxt] = 0ull;   // last read two barriers ago; safe to reset
        __syncthreads();
        int tmp = prev; prev = cur; cur = nxt; nxt = tmp;
    }
    __syncthreads();

    for (int k = t; k < NKP; k += NTHR) {
        int p = g_kp_sorted[b*NKP + k];
        int phys = (p & 15)*NTHR + (p >> 4);
        g_kp_xyz[(b*NKP+k)*3+0] = sxT[phys];
        g_kp_xyz[(b*NKP+k)*3+1] = syT[phys];
        g_kp_xyz[(b*NKP+k)*3+2] = szT[phys];
    }
    // export sorted structure for cell-pruned ball query
    for (int p = t; p < NPTS; p += NTHR) {
        int phys = (p & 15)*NTHR + (p >> 4);
        g_sorted4[b*NPTS + p] = make_float4(sxT[phys], syT[phys], szT[phys],
                                            __int_as_float((int)spermT[phys]));
    }
    for (int c = t; c < NCELLS; c += NTHR) g_cell_end[b*NCELLS + c] = (int)hist[c];
    if (t == 0) {
        g_grid[b*8+0] = gminx; g_grid[b*8+1] = gminy; g_grid[b*8+2] = gminz;
        g_grid[b*8+3] = grx;   g_grid[b*8+4] = gry;   g_grid[b*8+5] = grz;
    }
}

// ============ K2: cell-pruned ball query (one warp per keypoint) ============
__global__ __launch_bounds__(256) void ballq_kernel() {
    int kp = blockIdx.x * 8 + (threadIdx.x >> 5);
    int b = kp >> 12, lane = threadIdx.x & 31;
    float kx = g_kp_xyz[kp*3+0], ky = g_kp_xyz[kp*3+1], kz = g_kp_xyz[kp*3+2];
    float gminx = g_grid[b*8+0], gminy = g_grid[b*8+1], gminz = g_grid[b*8+2];
    float grx = g_grid[b*8+3], gry = g_grid[b*8+4], grz = g_grid[b*8+5];
    const float4* sp4 = g_sorted4 + b*NPTS;
    const int* cend = g_cell_end + b*NCELLS;

    const float R = 1.6005f;
    int cx0 = max(0, min(15, (int)floorf((kx - R - gminx) * grx)));
    int cx1 = max(0, min(15, (int)floorf((kx + R - gminx) * grx)));
    int cy0 = max(0, min(15, (int)floorf((ky - R - gminy) * gry)));
    int cy1 = max(0, min(15, (int)floorf((ky + R - gminy) * gry)));
    int cz0 = max(0, min(1,  (int)floorf((kz - R - gminz) * grz)));
    int cz1 = max(0, min(1,  (int)floorf((kz + R - gminz) * grz)));

    int cnt = 0;
    unsigned lmask = (1u << lane) - 1u;
    for (int cy = cy0; cy <= cy1; cy++) {
        for (int cx = cx0; cx <= cx1; cx++) {
            int base = ((mort4(cy) << 1) | mort4(cx)) << 1;
            int c0 = base | cz0, c1 = base | cz1;
            int pstart = (c0 == 0) ? 0 : cend[c0-1];
            int pend = cend[c1];
            for (int p0 = pstart; p0 < pend; p0 += 32) {   // uniform trip count
                int p = p0 + lane;
                bool in = p < pend;
                float4 P = in ? sp4[p] : make_float4(1e30f, 1e30f, 1e30f, 0.f);
                float d2 = dist2_ref(kx - P.x, ky - P.y, kz - P.z);
                bool hit = in && (d2 < R2B_CONST);
                unsigned m = __ballot_sync(0xffffffffu, hit);
                if (hit) {
                    int pos = cnt + __popc(m & lmask);
                    if (pos < CCAP) {
                        g_cand_d[kp*CCAP + pos] = d2;
                        g_cand_i[kp*CCAP + pos] = __float_as_int(P.w);
                    }
                }
                cnt += __popc(m);
            }
        }
    }
    if (lane == 0) g_cand_cnt[kp] = (cnt < CCAP) ? cnt : CCAP;
}

// ============ K3: rank candidates (one warp per keypoint) ============
__global__ __launch_bounds__(256) void select_kernel() {
    __shared__ float sd[8*CCAP];
    __shared__ int   si[8*CCAP];
    int w = threadIdx.x >> 5, lane = threadIdx.x & 31;
    int kp = blockIdx.x * 8 + w;
    float* swd = sd + w*CCAP; int* swi = si + w*CCAP;
    int n = g_cand_cnt[kp];
    for (int c = lane; c < n; c += 32) {
        swd[c] = g_cand_d[kp*CCAP + c];
        swi[c] = g_cand_i[kp*CCAP + c];
    }
    __syncwarp();
    int na = 0;
    for (int c = lane; c < n; c += 32) {
        float dc = swd[c];
        int oc = swi[c];
        int rank = 0;
        for (int c2 = 0; c2 < n; c2++) {
            float dv = swd[c2];
            rank += (dv < dc) || (dv == dc && swi[c2] < oc);
        }
        if (rank < 32) g_nbr[kp*32 + rank] = oc;
        if (rank < 16 && dc < R2A_CONST) na++;
    }
    #pragma unroll
    for (int off = 16; off > 0; off >>= 1) na += __shfl_down_sync(0xffffffffu, na, off);
    if (lane == 0) {
        g_cnt_a[kp] = na;
        g_cnt_b[kp] = (n < 32) ? n : 32;
    }
}

// ============ K4: PointNet MLP + max pool, packed f32x2 FMA ============
__global__ __launch_bounds__(256) void mlp_kernel(const float* __restrict__ clouds,
                                                  const float* __restrict__ w1a,
                                                  const float* __restrict__ w2a,
                                                  const float* __restrict__ w1b,
                                                  const float* __restrict__ w2b) {
    int kp = blockIdx.x;
    int b  = kp >> 12;
    __shared__ float sg[32][5];
    __shared__ float h1bt[128*32];
    __shared__ float h1at[128*16];
    __shared__ int   s_ca, s_cb;
    int t = threadIdx.x;
    if (t == 0) { s_ca = g_cnt_a[kp]; s_cb = g_cnt_b[kp]; }
    __syncthreads();
    int ca = s_ca, cb2 = s_cb;

    if (t < 32 && t < cb2) {
        int pi = g_nbr[kp*32 + t];
        const float* cbase = clouds + (size_t)b*4*NPTS;
        sg[t][0] = cbase[pi]        - g_kp_xyz[kp*3+0];
        sg[t][1] = cbase[NPTS+pi]   - g_kp_xyz[kp*3+1];
        sg[t][2] = cbase[2*NPTS+pi] - g_kp_xyz[kp*3+2];
        sg[t][3] = cbase[3*NPTS+pi];
    }
    __syncthreads();

    for (int e = t; e < 128*32; e += 256) {
        int j = e & 31, i = e >> 5;
        float v = 0.f;
        if (j < cb2) {
            float a = __fmul_rn(sg[j][0], w1b[i]);
            a = fmaf(sg[j][1], w1b[128+i], a);
            a = fmaf(sg[j][2], w1b[256+i], a);
            a = fmaf(sg[j][3], w1b[384+i], a);
            v = fmaxf(a, 0.f);
        }
        h1bt[i*32 + j] = v;
    }
    for (int e = t; e < 128*16; e += 256) {
        int j = e & 15, i = e >> 4;
        float v = 0.f;
        if (j < ca) {
            float a = __fmul_rn(sg[j][0], w1a[i]);
            a = fmaf(sg[j][1], w1a[128+i], a);
            a = fmaf(sg[j][2], w1a[256+i], a);
            a = fmaf(sg[j][3], w1a[384+i], a);
            v = fmaxf(a, 0.f);
        }
        h1at[i*16 + j] = v;
    }
    __syncthreads();

    // scale b: 16 packed accumulators (32 channels-of-j), identical fp32 math
    unsigned long long accb[16];
    #pragma unroll
    for (int j = 0; j < 16; j++) accb[j] = 0ull;
    for (int i = 0; i < 128; i++) {
        unsigned long long wd = dup2(__ldg(&w2b[i*256 + t]));
        const ulonglong2* hq = reinterpret_cast<const ulonglong2*>(h1bt + i*32);
        #pragma unroll
        for (int j4 = 0; j4 < 8; j4++) {
            ulonglong2 h2 = hq[j4];
            ffma2(accb[j4*2+0], h2.x, wd);
            ffma2(accb[j4*2+1], h2.y, wd);
        }
    }
    float bestb = 0.f;
    #pragma unroll
    for (int j = 0; j < 16; j++) bestb = fmaxf(bestb, pairmax(accb[j]));

    unsigned long long acca[8];
    #pragma unroll
    for (int j = 0; j < 8; j++) acca[j] = 0ull;
    for (int i = 0; i < 128; i++) {
        unsigned long long wd = dup2(__ldg(&w2a[i*256 + t]));
        const ulonglong2* hq = reinterpret_cast<const ulonglong2*>(h1at + i*16);
        #pragma unroll
        for (int j4 = 0; j4 < 4; j4++) {
            ulonglong2 h2 = hq[j4];
            ffma2(acca[j4*2+0], h2.x, wd);
            ffma2(acca[j4*2+1], h2.y, wd);
        }
    }
    float besta = 0.f;
    #pragma unroll
    for (int j = 0; j < 8; j++) besta = fmaxf(besta, pairmax(acca[j]));

    g_pooled[kp*512 + t]       = besta;
    g_pooled[kp*512 + 256 + t] = bestb;
}

// ============ K5: fusion + output (16 kp per block) ============
__global__ __launch_bounds__(128) void fuse_kernel(const float* __restrict__ wf,
                                                   float* __restrict__ out) {
    int kp0 = blockIdx.x * 16;
    __shared__ float sp[512*16];
    int t = threadIdx.x;
    for (int e = t; e < 512*16; e += 128) {
        int c = e & 511, q = e >> 9;
        sp[c*16 + q] = g_pooled[(size_t)(kp0 + q)*512 + c];
    }
    __syncthreads();
    unsigned long long acc[8];
    #pragma unroll
    for (int q = 0; q < 8; q++) acc[q] = 0ull;
    for (int c = 0; c < 512; c++) {
        unsigned long long wd = dup2(__ldg(&wf[c*128 + t]));
        const ulonglong2* pr = reinterpret_cast<const ulonglong2*>(sp + c*16);
        #pragma unroll
        for (int q4 = 0; q4 < 4; q4++) {
            ulonglong2 p2 = pr[q4];
            ffma2(acc[q4*2+0], p2.x, wd);
            ffma2(acc[q4*2+1], p2.y, wd);
        }
    }
    #pragma unroll
    for (int q = 0; q < 8; q++) {
        unsigned lo, hi;
        asm("mov.b64 {%0, %1}, %2;" : "=r"(lo), "=r"(hi) : "l"(acc[q]));
        out[(size_t)(kp0+q*2+0)*131 + 3 + t] = fmaxf(__uint_as_float(lo), 0.f);
        out[(size_t)(kp0+q*2+1)*131 + 3 + t] = fmaxf(__uint_as_float(hi), 0.f);
    }
    if (t < 48) {
        int q = t / 3, comp = t % 3;
        out[(size_t)(kp0+q)*131 + comp] = g_kp_xyz[(kp0+q)*3 + comp];
    }
}

extern "C" void kernel_launch(void* const* d_in, const int* in_sizes, int n_in,
                              void* d_out, int out_size) {
    const float* clouds = (const float*)d_in[0];
    const float* w1a    = (const float*)d_in[1];
    const float* w2a    = (const float*)d_in[2];
    const float* w1b    = (const float*)d_in[3];
    const float* w2b    = (const float*)d_in[4];
    const float* wf     = (const float*)d_in[5];
    float* out = (float*)d_out;

    int fps_smem = 3*NPTS*4 + NPTS*2 + NCELLS*4 + 24 + 24 + 16;
    cudaFuncSetAttribute(fps_kernel, cudaFuncAttributeMaxDynamicSharedMemorySize, fps_smem);
    fps_kernel<<<BATCH, NTHR, fps_smem>>>(clouds);

    ballq_kernel<<<TOTKP/8, 256>>>();
    select_kernel<<<TOTKP/8, 256>>>();
    mlp_kernel<<<TOTKP, 256>>>(clouds, w1a, w2a, w1b, w2b);
    fuse_kernel<<<TOTKP/16, 128>>>(wf, out);
}

// round 8
// speedup vs baseline: 2.1868x; 1.0919x over previous
#include <cuda_runtime.h>

#define BATCH 2
#define NPTS  16384
#define NKP   4096
#define TOTKP (BATCH*NKP)
#define CCAP  384
#define R2A_CONST ((float)(0.8*0.8))
#define R2B_CONST ((float)(1.6*1.6))
#define NTHR  1024
#define PPT   16
#define NCELLS 512

__device__ float g_kp_xyz[TOTKP*3];
__device__ int   g_kp_sorted[TOTKP];
__device__ float4 g_sorted4[BATCH*NPTS];
__device__ int   g_cell_end[BATCH*NCELLS];
__device__ float g_grid[BATCH*8];
__device__ float g_cand_d[TOTKP*CCAP];
__device__ int   g_cand_i[TOTKP*CCAP];
__device__ int   g_cand_cnt[TOTKP];
__device__ int   g_nbr[TOTKP*32];
__device__ int   g_cnt_a[TOTKP];
__device__ int   g_cnt_b[TOTKP];
__device__ float g_pooled[TOTKP*512];

__device__ __forceinline__ float dist2_ref(float dx, float dy, float dz) {
    return __fadd_rn(__fadd_rn(__fmul_rn(dx,dx), __fmul_rn(dy,dy)), __fmul_rn(dz,dz));
}
__device__ __forceinline__ unsigned fenc(float f) {   // monotone for f >= 0
    return __float_as_uint(f) | 0x80000000u;
}
__device__ __forceinline__ unsigned fenc_s(float f) { // full monotone encode
    unsigned u = __float_as_uint(f);
    return (u & 0x80000000u) ? ~u : (u | 0x80000000u);
}
__device__ __forceinline__ float fdec_s(unsigned u) {
    return __uint_as_float((u & 0x80000000u) ? (u & 0x7fffffffu) : ~u);
}
__device__ __forceinline__ int mort4(int v) {
    v = (v | (v << 2)) & 0x33;
    v = (v | (v << 1)) & 0x55;
    return v;
}
// packed f32x2 FMA helpers (bit-identical IEEE fp32 per lane)
__device__ __forceinline__ void ffma2(unsigned long long& acc, unsigned long long h2,
                                      unsigned long long w2) {
    asm("fma.rn.f32x2 %0, %1, %2, %0;" : "+l"(acc) : "l"(h2), "l"(w2));
}
__device__ __forceinline__ unsigned long long dup2(float w) {
    unsigned long long r;
    asm("mov.b64 %0, {%1, %1};" : "=l"(r) : "r"(__float_as_uint(w)));
    return r;
}
__device__ __forceinline__ float pairmax(unsigned long long a) {
    unsigned lo, hi;
    asm("mov.b64 {%0, %1}, %2;" : "=r"(lo), "=r"(hi) : "l"(a));
    return fmaxf(__uint_as_float(lo), __uint_as_float(hi));
}

// ============ K1: FPS — bucket skip + atomic-free double-buffered merge ============
extern __shared__ unsigned char dsm[];

__global__ __launch_bounds__(NTHR,1) void fps_kernel(const float* __restrict__ clouds) {
    int b = blockIdx.x;
    float* sxT = (float*)dsm;
    float* syT = sxT + NPTS;
    float* szT = syT + NPTS;
    unsigned short* spermT = (unsigned short*)(szT + NPTS);
    unsigned int*   hist   = (unsigned int*)(spermT + NPTS);
    uint2* wk0 = (uint2*)(hist + NCELLS);          // key buffer, parity 0 (32 warps)
    uint2* wk1 = wk0 + 32;                          // parity 1
    unsigned int* s_bb = (unsigned int*)(wk1 + 32); // [0..5] bbox encoded
    int* s_p0 = (int*)(s_bb + 6);                   // sorted pos of orig point 0

    const float* cb = clouds + (size_t)b*4*NPTS;
    int t = threadIdx.x, lane = t & 31, w = t >> 5;

    if (t < 3)      s_bb[t] = 0xFFFFFFFFu;
    else if (t < 6) s_bb[t] = 0u;
    for (int c = t; c < NCELLS; c += NTHR) hist[c] = 0;
    __syncthreads();
    {
        float mnx=1e30f,mny=1e30f,mnz=1e30f,mxx=-1e30f,mxy=-1e30f,mxz=-1e30f;
        for (int j = 0; j < PPT; j++) {
            int i = t + j*NTHR;
            float x = cb[i], y = cb[NPTS+i], z = cb[2*NPTS+i];
            mnx = fminf(mnx,x); mny = fminf(mny,y); mnz = fminf(mnz,z);
            mxx = fmaxf(mxx,x); mxy = fmaxf(mxy,y); mxz = fmaxf(mxz,z);
        }
        #pragma unroll
        for (int off = 16; off > 0; off >>= 1) {
            mnx = fminf(mnx, __shfl_down_sync(0xffffffffu, mnx, off));
            mny = fminf(mny, __shfl_down_sync(0xffffffffu, mny, off));
            mnz = fminf(mnz, __shfl_down_sync(0xffffffffu, mnz, off));
            mxx = fmaxf(mxx, __shfl_down_sync(0xffffffffu, mxx, off));
            mxy = fmaxf(mxy, __shfl_down_sync(0xffffffffu, mxy, off));
            mxz = fmaxf(mxz, __shfl_down_sync(0xffffffffu, mxz, off));
        }
        if (lane == 0) {
            atomicMin(&s_bb[0], fenc_s(mnx));
            atomicMin(&s_bb[1], fenc_s(mny));
            atomicMin(&s_bb[2], fenc_s(mnz));
            atomicMax(&s_bb[3], fenc_s(mxx));
            atomicMax(&s_bb[4], fenc_s(mxy));
            atomicMax(&s_bb[5], fenc_s(mxz));
        }
    }
    __syncthreads();
    float gminx = fdec_s(s_bb[0]), gminy = fdec_s(s_bb[1]), gminz = fdec_s(s_bb[2]);
    float grx = 16.0f / fmaxf(fdec_s(s_bb[3]) - gminx, 1e-9f);
    float gry = 16.0f / fmaxf(fdec_s(s_bb[4]) - gminy, 1e-9f);
    float grz = 2.0f  / fmaxf(fdec_s(s_bb[5]) - gminz, 1e-9f);

    for (int j = 0; j < PPT; j++) {
        int i = t + j*NTHR;
        int cx = min(15, (int)((cb[i]        - gminx) * grx));
        int cy = min(15, (int)((cb[NPTS+i]   - gminy) * gry));
        int cz = min(1,  (int)((cb[2*NPTS+i] - gminz) * grz));
        int cell = (((mort4(cy) << 1) | mort4(cx)) << 1) | cz;
        atomicAdd(&hist[cell], 1u);
    }
    __syncthreads();
    for (int off = 1; off < NCELLS; off <<= 1) {
        unsigned v = 0;
        if (t < NCELLS && t >= off) v = hist[t-off];
        __syncthreads();
        if (t < NCELLS) hist[t] += v;
        __syncthreads();
    }
    {
        unsigned v = (t == 0) ? 0u : ((t < NCELLS) ? hist[t-1] : 0u);
        __syncthreads();
        if (t < NCELLS) hist[t] = v;
        __syncthreads();
    }
    for (int j = 0; j < PPT; j++) {
        int i = t + j*NTHR;
        float x = cb[i], y = cb[NPTS+i], z = cb[2*NPTS+i];
        int cx = min(15, (int)((x - gminx) * grx));
        int cy = min(15, (int)((y - gminy) * gry));
        int cz = min(1,  (int)((z - gminz) * grz));
        int cell = (((mort4(cy) << 1) | mort4(cx)) << 1) | cz;
        int p = (int)atomicAdd(&hist[cell], 1u);
        int phys = (p & 15)*NTHR + (p >> 4);
        sxT[phys] = x; syT[phys] = y; szT[phys] = z;
        spermT[phys] = (unsigned short)i;
        if (i == 0) *s_p0 = p;   // iter0 winner = orig point 0
    }
    __syncthreads();

    float dmin[PPT];
    float bxmin=1e30f, bymin=1e30f, bzmin=1e30f, bxmax=-1e30f, bymax=-1e30f, bzmax=-1e30f;
    #pragma unroll
    for (int j = 0; j < PPT; j++) {
        dmin[j] = 1e10f;
        float x = sxT[j*NTHR + t], y = syT[j*NTHR + t], z = szT[j*NTHR + t];
        bxmin = fminf(bxmin,x); bymin = fminf(bymin,y); bzmin = fminf(bzmin,z);
        bxmax = fmaxf(bxmax,x); bymax = fmaxf(bymax,y); bzmax = fmaxf(bzmax,z);
    }
    float bestv = 1e10f; int bestorig = 0x3fff; int bestsorted = t*PPT;
    unsigned wkh = 0u, wkl = 0u;       // warp's cached champion key (always valid)
    int last = *s_p0;                   // sorted position of original point 0

    for (int it = 0; it < NKP; ++it) {
        if (t == 0) g_kp_sorted[b*NKP + it] = last;
        if (it == NKP-1) break;

        int lphys = (last & 15)*NTHR + (last >> 4);
        float lx = sxT[lphys], ly = syT[lphys], lz = szT[lphys];

        float dx = fmaxf(fmaxf(bxmin - lx, lx - bxmax), 0.f);
        float dy = fmaxf(fmaxf(bymin - ly, ly - bymax), 0.f);
        float dz = fmaxf(fmaxf(bzmin - lz, lz - bzmax), 0.f);
        float d2b = fmaf(dx, dx, fmaf(dy, dy, dz*dz));
        bool need = (d2b * 0.99999f) < bestv;

        if (need) {
            float bv = -1.f; int bo = 0x3fff, bs = t*PPT;
            #pragma unroll
            for (int j = 0; j < PPT; j++) {
                int phys = j*NTHR + t;
                float d  = dist2_ref(sxT[phys]-lx, syT[phys]-ly, szT[phys]-lz);
                float nd = fminf(dmin[j], d);
                dmin[j] = nd;
                int o = (int)spermT[phys];
                if (nd > bv || (nd == bv && o < bo)) { bv = nd; bo = o; bs = t*PPT + j; }
            }
            bestv = bv; bestorig = bo; bestsorted = bs;
        }
        unsigned m = __ballot_sync(0xffffffffu, need);
        if (m) {   // refresh warp champion key (cached key valid while skipping)
            unsigned fv = fenc(bestv);
            wkh = __reduce_max_sync(0xffffffffu, fv);
            unsigned lo = (fv == wkh) ? (((unsigned)(0x3fff - bestorig) << 14) | (unsigned)bestsorted) : 0u;
            wkl = __reduce_max_sync(0xffffffffu, lo);
        }
        uint2* wkb = (it & 1) ? wk1 : wk0;
        if (lane == 0) wkb[w] = make_uint2(wkh, wkl);   // own slot, plain STS.64
        __syncthreads();
        // stage 2 in every warp: reduce the 32 warp keys, winner to registers
        uint2 k = wkb[lane];
        unsigned mh = __reduce_max_sync(0xffffffffu, k.x);
        unsigned ml = __reduce_max_sync(0xffffffffu, (k.x == mh) ? k.y : 0u);
        last = (int)(ml & 0x3fffu);
        // no second barrier: next iteration writes the OTHER parity buffer, and
        // a wrap-around rewrite of this buffer is fenced by the next BAR
    }
    __syncthreads();

    for (int k = t; k < NKP; k += NTHR) {
        int p = g_kp_sorted[b*NKP + k];
        int phys = (p & 15)*NTHR + (p >> 4);
        g_kp_xyz[(b*NKP+k)*3+0] = sxT[phys];
        g_kp_xyz[(b*NKP+k)*3+1] = syT[phys];
        g_kp_xyz[(b*NKP+k)*3+2] = szT[phys];
    }
    // export sorted structure for cell-pruned ball query
    for (int p = t; p < NPTS; p += NTHR) {
        int phys = (p & 15)*NTHR + (p >> 4);
        g_sorted4[b*NPTS + p] = make_float4(sxT[phys], syT[phys], szT[phys],
                                            __int_as_float((int)spermT[phys]));
    }
    for (int c = t; c < NCELLS; c += NTHR) g_cell_end[b*NCELLS + c] = (int)hist[c];
    if (t == 0) {
        g_grid[b*8+0] = gminx; g_grid[b*8+1] = gminy; g_grid[b*8+2] = gminz;
        g_grid[b*8+3] = grx;   g_grid[b*8+4] = gry;   g_grid[b*8+5] = grz;
    }
}

// ============ K2: cell-pruned ball query (one warp per keypoint) ============
__global__ __launch_bounds__(256) void ballq_kernel() {
    int kp = blockIdx.x * 8 + (threadIdx.x >> 5);
    int b = kp >> 12, lane = threadIdx.x & 31;
    float kx = g_kp_xyz[kp*3+0], ky = g_kp_xyz[kp*3+1], kz = g_kp_xyz[kp*3+2];
    float gminx = g_grid[b*8+0], gminy = g_grid[b*8+1], gminz = g_grid[b*8+2];
    float grx = g_grid[b*8+3], gry = g_grid[b*8+4], grz = g_grid[b*8+5];
    const float4* sp4 = g_sorted4 + b*NPTS;
    const int* cend = g_cell_end + b*NCELLS;

    const float R = 1.6005f;
    int cx0 = max(0, min(15, (int)floorf((kx - R - gminx) * grx)));
    int cx1 = max(0, min(15, (int)floorf((kx + R - gminx) * grx)));
    int cy0 = max(0, min(15, (int)floorf((ky - R - gminy) * gry)));
    int cy1 = max(0, min(15, (int)floorf((ky + R - gminy) * gry)));
    int cz0 = max(0, min(1,  (int)floorf((kz - R - gminz) * grz)));
    int cz1 = max(0, min(1,  (int)floorf((kz + R - gminz) * grz)));

    int cnt = 0;
    unsigned lmask = (1u << lane) - 1u;
    for (int cy = cy0; cy <= cy1; cy++) {
        for (int cx = cx0; cx <= cx1; cx++) {
            int base = ((mort4(cy) << 1) | mort4(cx)) << 1;
            int c0 = base | cz0, c1 = base | cz1;
            int pstart = (c0 == 0) ? 0 : cend[c0-1];
            int pend = cend[c1];
            for (int p0 = pstart; p0 < pend; p0 += 32) {   // uniform trip count
                int p = p0 + lane;
                bool in = p < pend;
                float4 P = in ? sp4[p] : make_float4(1e30f, 1e30f, 1e30f, 0.f);
                float d2 = dist2_ref(kx - P.x, ky - P.y, kz - P.z);
                bool hit = in && (d2 < R2B_CONST);
                unsigned m = __ballot_sync(0xffffffffu, hit);
                if (hit) {
                    int pos = cnt + __popc(m & lmask);
                    if (pos < CCAP) {
                        g_cand_d[kp*CCAP + pos] = d2;
                        g_cand_i[kp*CCAP + pos] = __float_as_int(P.w);
                    }
                }
                cnt += __popc(m);
            }
        }
    }
    if (lane == 0) g_cand_cnt[kp] = (cnt < CCAP) ? cnt : CCAP;
}

// ============ K3: rank candidates (one warp per keypoint) ============
__global__ __launch_bounds__(256) void select_kernel() {
    __shared__ float sd[8*CCAP];
    __shared__ int   si[8*CCAP];
    int w = threadIdx.x >> 5, lane = threadIdx.x & 31;
    int kp = blockIdx.x * 8 + w;
    float* swd = sd + w*CCAP; int* swi = si + w*CCAP;
    int n = g_cand_cnt[kp];
    for (int c = lane; c < n; c += 32) {
        swd[c] = g_cand_d[kp*CCAP + c];
        swi[c] = g_cand_i[kp*CCAP + c];
    }
    __syncwarp();
    int na = 0;
    for (int c = lane; c < n; c += 32) {
        float dc = swd[c];
        int oc = swi[c];
        int rank = 0;
        for (int c2 = 0; c2 < n; c2++) {
            float dv = swd[c2];
            rank += (dv < dc) || (dv == dc && swi[c2] < oc);
        }
        if (rank < 32) g_nbr[kp*32 + rank] = oc;
        if (rank < 16 && dc < R2A_CONST) na++;
    }
    #pragma unroll
    for (int off = 16; off > 0; off >>= 1) na += __shfl_down_sync(0xffffffffu, na, off);
    if (lane == 0) {
        g_cnt_a[kp] = na;
        g_cnt_b[kp] = (n < 32) ? n : 32;
    }
}

// ============ K4: PointNet MLP + max pool, packed f32x2 FMA ============
__global__ __launch_bounds__(256) void mlp_kernel(const float* __restrict__ clouds,
                                                  const float* __restrict__ w1a,
                                                  const float* __restrict__ w2a,
                                                  const float* __restrict__ w1b,
                                                  const float* __restrict__ w2b) {
    int kp = blockIdx.x;
    int b  = kp >> 12;
    __shared__ float sg[32][5];
    __shared__ float h1bt[128*32];
    __shared__ float h1at[128*16];
    __shared__ int   s_ca, s_cb;
    int t = threadIdx.x;
    if (t == 0) { s_ca = g_cnt_a[kp]; s_cb = g_cnt_b[kp]; }
    __syncthreads();
    int ca = s_ca, cb2 = s_cb;

    if (t < 32 && t < cb2) {
        int pi = g_nbr[kp*32 + t];
        const float* cbase = clouds + (size_t)b*4*NPTS;
        sg[t][0] = cbase[pi]        - g_kp_xyz[kp*3+0];
        sg[t][1] = cbase[NPTS+pi]   - g_kp_xyz[kp*3+1];
        sg[t][2] = cbase[2*NPTS+pi] - g_kp_xyz[kp*3+2];
        sg[t][3] = cbase[3*NPTS+pi];
    }
    __syncthreads();

    for (int e = t; e < 128*32; e += 256) {
        int j = e & 31, i = e >> 5;
        float v = 0.f;
        if (j < cb2) {
            float a = __fmul_rn(sg[j][0], w1b[i]);
            a = fmaf(sg[j][1], w1b[128+i], a);
            a = fmaf(sg[j][2], w1b[256+i], a);
            a = fmaf(sg[j][3], w1b[384+i], a);
            v = fmaxf(a, 0.f);
        }
        h1bt[i*32 + j] = v;
    }
    for (int e = t; e < 128*16; e += 256) {
        int j = e & 15, i = e >> 4;
        float v = 0.f;
        if (j < ca) {
            float a = __fmul_rn(sg[j][0], w1a[i]);
            a = fmaf(sg[j][1], w1a[128+i], a);
            a = fmaf(sg[j][2], w1a[256+i], a);
            a = fmaf(sg[j][3], w1a[384+i], a);
            v = fmaxf(a, 0.f);
        }
        h1at[i*16 + j] = v;
    }
    __syncthreads();

    unsigned long long accb[16];
    #pragma unroll
    for (int j = 0; j < 16; j++) accb[j] = 0ull;
    for (int i = 0; i < 128; i++) {
        unsigned long long wd = dup2(__ldg(&w2b[i*256 + t]));
        const ulonglong2* hq = reinterpret_cast<const ulonglong2*>(h1bt + i*32);
        #pragma unroll
        for (int j4 = 0; j4 < 8; j4++) {
            ulonglong2 h2 = hq[j4];
            ffma2(accb[j4*2+0], h2.x, wd);
            ffma2(accb[j4*2+1], h2.y, wd);
        }
    }
    float bestb = 0.f;
    #pragma unroll
    for (int j = 0; j < 16; j++) bestb = fmaxf(bestb, pairmax(accb[j]));

    unsigned long long acca[8];
    #pragma unroll
    for (int j = 0; j < 8; j++) acca[j] = 0ull;
    for (int i = 0; i < 128; i++) {
        unsigned long long wd = dup2(__ldg(&w2a[i*256 + t]));
        const ulonglong2* hq = reinterpret_cast<const ulonglong2*>(h1at + i*16);
        #pragma unroll
        for (int j4 = 0; j4 < 4; j4++) {
            ulonglong2 h2 = hq[j4];
            ffma2(acca[j4*2+0], h2.x, wd);
            ffma2(acca[j4*2+1], h2.y, wd);
        }
    }
    float besta = 0.f;
    #pragma unroll
    for (int j = 0; j < 8; j++) besta = fmaxf(besta, pairmax(acca[j]));

    g_pooled[kp*512 + t]       = besta;
    g_pooled[kp*512 + 256 + t] = bestb;
}

// ============ K5: fusion + output (16 kp per block) ============
__global__ __launch_bounds__(128) void fuse_kernel(const float* __restrict__ wf,
                                                   float* __restrict__ out) {
    int kp0 = blockIdx.x * 16;
    __shared__ float sp[512*16];
    int t = threadIdx.x;
    for (int e = t; e < 512*16; e += 128) {
        int c = e & 511, q = e >> 9;
        sp[c*16 + q] = g_pooled[(size_t)(kp0 + q)*512 + c];
    }
    __syncthreads();
    unsigned long long acc[8];
    #pragma unroll
    for (int q = 0; q < 8; q++) acc[q] = 0ull;
    for (int c = 0; c < 512; c++) {
        unsigned long long wd = dup2(__ldg(&wf[c*128 + t]));
        const ulonglong2* pr = reinterpret_cast<const ulonglong2*>(sp + c*16);
        #pragma unroll
        for (int q4 = 0; q4 < 4; q4++) {
            ulonglong2 p2 = pr[q4];
            ffma2(acc[q4*2+0], p2.x, wd);
            ffma2(acc[q4*2+1], p2.y, wd);
        }
    }
    #pragma unroll
    for (int q = 0; q < 8; q++) {
        unsigned lo, hi;
        asm("mov.b64 {%0, %1}, %2;" : "=r"(lo), "=r"(hi) : "l"(acc[q]));
        out[(size_t)(kp0+q*2+0)*131 + 3 + t] = fmaxf(__uint_as_float(lo), 0.f);
        out[(size_t)(kp0+q*2+1)*131 + 3 + t] = fmaxf(__uint_as_float(hi), 0.f);
    }
    if (t < 48) {
        int q = t / 3, comp = t % 3;
        out[(size_t)(kp0+q)*131 + comp] = g_kp_xyz[(kp0+q)*3 + comp];
    }
}

extern "C" void kernel_launch(void* const* d_in, const int* in_sizes, int n_in,
                              void* d_out, int out_size) {
    const float* clouds = (const float*)d_in[0];
    const float* w1a    = (const float*)d_in[1];
    const float* w2a    = (const float*)d_in[2];
    const float* w1b    = (const float*)d_in[3];
    const float* w2b    = (const float*)d_in[4];
    const float* wf     = (const float*)d_in[5];
    float* out = (float*)d_out;

    // coords + perm + hist + 2x32 uint2 keys + bbox(6) + p0
    int fps_smem = 3*NPTS*4 + NPTS*2 + NCELLS*4 + 2*32*8 + 6*4 + 16;
    cudaFuncSetAttribute(fps_kernel, cudaFuncAttributeMaxDynamicSharedMemorySize, fps_smem);
    fps_kernel<<<BATCH, NTHR, fps_smem>>>(clouds);

    ballq_kernel<<<TOTKP/8, 256>>>();
    select_kernel<<<TOTKP/8, 256>>>();
    mlp_kernel<<<TOTKP, 256>>>(clouds, w1a, w2a, w1b, w2b);
    fuse_kernel<<<TOTKP/16, 128>>>(wf, out);
}